// round 8
// baseline (speedup 1.0000x reference)
#include <cuda_runtime.h>
#include <cuda_fp16.h>

#define N_NODES 100000
#define N_EDGES 3200000
#define F_IN    256
#define F_HID   64
#define F_OUT   40
#define SCAN_B  512
#define N_SCANB ((N_NODES + SCAN_B - 1) / SCAN_B)   // 196

// ---------------- scratch (device globals: alloc-free) ----------------
__device__ int     g_dege  [N_NODES];
__device__ float   g_dinv  [N_NODES];
__device__ int     g_rowptr[N_NODES];
__device__ int     g_cursor[N_NODES];
__device__ int     g_bsum  [256];
__device__ int2    g_edges [N_EDGES];     // dst-sorted: {src, norm bits}
__device__ __half2 g_h   [N_NODES * 32];  // h1, fp16 pairs (64 feats)
__device__ float   g_agg1[N_NODES * 64];  // fp32 aggregation
__device__ __half2 g_h2  [N_NODES * 20];  // h2, fp16 pairs (40 feats)

// ---------------- degree / norm prep ----------------
__global__ void k_init_deg() {
    int n = blockIdx.x * blockDim.x + threadIdx.x;
    if (n < N_NODES) g_dege[n] = 0;
}

__global__ void k_count_deg(const int* __restrict__ ei) {
    int e = blockIdx.x * blockDim.x + threadIdx.x;
    if (e < N_EDGES) atomicAdd(&g_dege[__ldg(&ei[N_EDGES + e])], 1);
}

__global__ void k_dinv() {
    int n = blockIdx.x * blockDim.x + threadIdx.x;
    if (n < N_NODES) g_dinv[n] = rsqrtf((float)(g_dege[n] + 1));
}

// ---------------- exclusive scan of g_dege -> g_rowptr ----------------
__global__ __launch_bounds__(SCAN_B) void k_scan1() {
    __shared__ int sm[SCAN_B];
    int t = threadIdx.x;
    int i = blockIdx.x * SCAN_B + t;
    int v = (i < N_NODES) ? g_dege[i] : 0;
    sm[t] = v;
    __syncthreads();
    for (int o = 1; o < SCAN_B; o <<= 1) {
        int x = (t >= o) ? sm[t - o] : 0;
        __syncthreads();
        sm[t] += x;
        __syncthreads();
    }
    if (i < N_NODES) g_rowptr[i] = sm[t] - v;
    if (t == SCAN_B - 1) g_bsum[blockIdx.x] = sm[t];
}

__global__ __launch_bounds__(256) void k_scan2() {
    __shared__ int sm[256];
    int t = threadIdx.x;
    int v = (t < N_SCANB) ? g_bsum[t] : 0;
    sm[t] = v;
    __syncthreads();
    for (int o = 1; o < 256; o <<= 1) {
        int x = (t >= o) ? sm[t - o] : 0;
        __syncthreads();
        sm[t] += x;
        __syncthreads();
    }
    g_bsum[t] = sm[t] - v;
}

__global__ void k_scan3() {
    int i = blockIdx.x * blockDim.x + threadIdx.x;
    if (i < N_NODES) {
        int r = g_rowptr[i] + g_bsum[i / SCAN_B];
        g_rowptr[i] = r;
        g_cursor[i] = r;
    }
}

__global__ void k_sort(const int* __restrict__ ei) {
    int e = blockIdx.x * blockDim.x + threadIdx.x;
    if (e < N_EDGES) {
        int s = __ldg(&ei[e]);
        int d = __ldg(&ei[N_EDGES + e]);
        float nm = g_dinv[s] * g_dinv[d];
        int pos = atomicAdd(&g_cursor[d], 1);
        g_edges[pos] = make_int2(s, __float_as_int(nm));
    }
}

// ------- GEMM1: h = x @ W1, register-blocked 2 nodes x 32 outputs/thread -------
// Block = 256 nodes. 8 warps: grp = wid>>1 covers 64 nodes, jhalf = wid&1 covers
// outputs [jhalf*32, +32). All lanes of a warp share jhalf -> every w LDS is a
// single-address broadcast (conflict-free). 8 LDS.128 per K-step serve 64 FMAs.
__global__ __launch_bounds__(256) void k_gemm1(const float* __restrict__ x,
                                               const float* __restrict__ W1) {
    __shared__ float w[128 * 64];
    int tid   = threadIdx.x;
    int wid   = tid >> 5;
    int lane  = tid & 31;
    int jhalf = wid & 1;          // output half
    int grp   = wid >> 1;         // node group (0..3), 64 nodes each
    int node0 = blockIdx.x * 256 + grp * 64 + lane * 2;
    bool v0 = node0     < N_NODES;
    bool v1 = node0 + 1 < N_NODES;

    float acc0[32], acc1[32];
#pragma unroll
    for (int j = 0; j < 32; j++) { acc0[j] = 0.f; acc1[j] = 0.f; }

#pragma unroll 1
    for (int kb = 0; kb < 2; kb++) {
        const float4* wsrc = (const float4*)(W1 + kb * 128 * 64);
        float4* wdst = (float4*)w;
#pragma unroll
        for (int i = 0; i < 8; i++)
            wdst[tid + i * 256] = wsrc[tid + i * 256];
        __syncthreads();

        const float4* xr0 = (const float4*)(x + (size_t)node0 * F_IN + kb * 128);
        const float4* xr1 = (const float4*)(x + (size_t)(node0 + 1) * F_IN + kb * 128);
#pragma unroll 4
        for (int k4 = 0; k4 < 32; k4++) {
            float4 xa = v0 ? xr0[k4] : make_float4(0.f, 0.f, 0.f, 0.f);
            float4 xb = v1 ? xr1[k4] : make_float4(0.f, 0.f, 0.f, 0.f);
#pragma unroll
            for (int kk = 0; kk < 4; kk++) {
                float xka = (kk == 0) ? xa.x : (kk == 1) ? xa.y : (kk == 2) ? xa.z : xa.w;
                float xkb = (kk == 0) ? xb.x : (kk == 1) ? xb.y : (kk == 2) ? xb.z : xb.w;
                const float4* wr = (const float4*)(w + (k4 * 4 + kk) * 64 + jhalf * 32);
#pragma unroll
                for (int j = 0; j < 8; j++) {
                    float4 wv = wr[j];          // broadcast: same addr for all lanes
                    acc0[4 * j + 0] += xka * wv.x;  acc1[4 * j + 0] += xkb * wv.x;
                    acc0[4 * j + 1] += xka * wv.y;  acc1[4 * j + 1] += xkb * wv.y;
                    acc0[4 * j + 2] += xka * wv.z;  acc1[4 * j + 2] += xkb * wv.z;
                    acc0[4 * j + 3] += xka * wv.w;  acc1[4 * j + 3] += xkb * wv.w;
                }
            }
        }
        __syncthreads();
    }

    if (v0) {
        __half2* o = &g_h[(size_t)node0 * 32 + jhalf * 16];
#pragma unroll
        for (int j = 0; j < 16; j++) o[j] = __floats2half2_rn(acc0[2 * j], acc0[2 * j + 1]);
    }
    if (v1) {
        __half2* o = &g_h[(size_t)(node0 + 1) * 32 + jhalf * 16];
#pragma unroll
        for (int j = 0; j < 16; j++) o[j] = __floats2half2_rn(acc1[2 * j], acc1[2 * j + 1]);
    }
}

// ------- layer-1 aggregation: warp/node, batch-8 MLP on full groups + tail -------
__global__ __launch_bounds__(256) void k_agg1() {
    int node = (blockIdx.x * 256 + threadIdx.x) >> 5;
    int lane = threadIdx.x & 31;
    if (node >= N_NODES) return;

    float dv = g_dinv[node];
    float s2 = dv * dv;
    float2 self = __half22float2(g_h[node * 32 + lane]);
    float a0 = s2 * self.x;
    float a1 = s2 * self.y;

    int start = g_rowptr[node];
    int cnt   = g_dege[node];
    for (int base = 0; base < cnt; base += 32) {
        int idx = base + lane;
        int2 rec = (idx < cnt) ? g_edges[start + idx] : make_int2(0, 0);
        int m = min(32, cnt - base);
        int j = 0;
        for (; j + 8 <= m; j += 8) {
            float  nms[8];
            float2 fv [8];
#pragma unroll
            for (int u = 0; u < 8; u++) {
                int src = __shfl_sync(0xFFFFFFFFu, rec.x, j + u);
                nms[u]  = __int_as_float(__shfl_sync(0xFFFFFFFFu, rec.y, j + u));
                fv[u]   = __half22float2(g_h[src * 32 + lane]);
            }
#pragma unroll
            for (int u = 0; u < 8; u++) { a0 += nms[u] * fv[u].x; a1 += nms[u] * fv[u].y; }
        }
        for (; j < m; j++) {
            int   src = __shfl_sync(0xFFFFFFFFu, rec.x, j);
            float nm  = __int_as_float(__shfl_sync(0xFFFFFFFFu, rec.y, j));
            float2 f = __half22float2(g_h[src * 32 + lane]);
            a0 += nm * f.x;
            a1 += nm * f.y;
        }
    }
    ((float2*)&g_agg1[node * 64])[lane] = make_float2(a0, a1);
}

// ---------------- GEMM2: h2 = relu(agg1 + b1) @ W2, fp16 out ----------------
__global__ __launch_bounds__(256) void k_gemm2(const float* __restrict__ W2,
                                               const float* __restrict__ b1) {
    __shared__ float w[64 * 40];
    __shared__ float bs[64];
    int node = blockIdx.x * 256 + threadIdx.x;

    const float4* wsrc = (const float4*)W2;
    float4* wdst = (float4*)w;
    for (int i = threadIdx.x; i < 64 * 10; i += 256) wdst[i] = wsrc[i];
    if (threadIdx.x < 64) bs[threadIdx.x] = b1[threadIdx.x];
    __syncthreads();

    if (node >= N_NODES) return;

    float acc[40];
#pragma unroll
    for (int j = 0; j < 40; j++) acc[j] = 0.f;

    const float4* ar = (const float4*)&g_agg1[node * 64];
#pragma unroll 4
    for (int k4 = 0; k4 < 16; k4++) {
        float4 a = ar[k4];
#pragma unroll
        for (int kk = 0; kk < 4; kk++) {
            int k = k4 * 4 + kk;
            float av = (kk == 0) ? a.x : (kk == 1) ? a.y : (kk == 2) ? a.z : a.w;
            float v = fmaxf(av + bs[k], 0.f);
            const float4* wr = (const float4*)(w + k * 40);
#pragma unroll
            for (int j = 0; j < 10; j++) {
                float4 wv = wr[j];
                acc[4 * j + 0] += v * wv.x;
                acc[4 * j + 1] += v * wv.y;
                acc[4 * j + 2] += v * wv.z;
                acc[4 * j + 3] += v * wv.w;
            }
        }
    }

    __half2* out = &g_h2[node * 20];
#pragma unroll
    for (int j = 0; j < 20; j++)
        out[j] = __floats2half2_rn(acc[2 * j], acc[2 * j + 1]);
}

// -- layer-2 aggregation + b2 + log-softmax fused: warp/node, batch-8 + tail --
__global__ __launch_bounds__(256) void k_agg2(float* __restrict__ out,
                                              const float* __restrict__ b2) {
    int node = (blockIdx.x * 256 + threadIdx.x) >> 5;
    int lane = threadIdx.x & 31;
    if (node >= N_NODES) return;

    float dv = g_dinv[node];
    float s2 = dv * dv;
    float a0 = 0.f, a1 = 0.f;
    if (lane < 20) {
        float2 self = __half22float2(g_h2[node * 20 + lane]);
        a0 = s2 * self.x;
        a1 = s2 * self.y;
    }

    int start = g_rowptr[node];
    int cnt   = g_dege[node];
    for (int base = 0; base < cnt; base += 32) {
        int idx = base + lane;
        int2 rec = (idx < cnt) ? g_edges[start + idx] : make_int2(0, 0);
        int m = min(32, cnt - base);
        int j = 0;
        for (; j + 8 <= m; j += 8) {
            float  nms[8];
            float2 fv [8];
#pragma unroll
            for (int u = 0; u < 8; u++) {
                int src = __shfl_sync(0xFFFFFFFFu, rec.x, j + u);
                nms[u]  = __int_as_float(__shfl_sync(0xFFFFFFFFu, rec.y, j + u));
                fv[u]   = (lane < 20) ? __half22float2(g_h2[src * 20 + lane])
                                      : make_float2(0.f, 0.f);
            }
#pragma unroll
            for (int u = 0; u < 8; u++) { a0 += nms[u] * fv[u].x; a1 += nms[u] * fv[u].y; }
        }
        for (; j < m; j++) {
            int   src = __shfl_sync(0xFFFFFFFFu, rec.x, j);
            float nm  = __int_as_float(__shfl_sync(0xFFFFFFFFu, rec.y, j));
            if (lane < 20) {
                float2 f = __half22float2(g_h2[src * 20 + lane]);
                a0 += nm * f.x;
                a1 += nm * f.y;
            }
        }
    }

    float v0 = -3.4e38f, v1 = -3.4e38f;
    if (lane < 20) {
        v0 = a0 + __ldg(&b2[2 * lane]);
        v1 = a1 + __ldg(&b2[2 * lane + 1]);
    }

    float mx = fmaxf(v0, v1);
#pragma unroll
    for (int o = 16; o > 0; o >>= 1)
        mx = fmaxf(mx, __shfl_xor_sync(0xFFFFFFFFu, mx, o));

    float s = (lane < 20) ? (expf(v0 - mx) + expf(v1 - mx)) : 0.f;
#pragma unroll
    for (int o = 16; o > 0; o >>= 1)
        s += __shfl_xor_sync(0xFFFFFFFFu, s, o);

    float ls = logf(s);
    if (lane < 20)
        ((float2*)(out + (size_t)node * 40))[lane] = make_float2(v0 - mx - ls, v1 - mx - ls);
}

// ---------------- launch ----------------
extern "C" void kernel_launch(void* const* d_in, const int* in_sizes, int n_in,
                              void* d_out, int out_size) {
    const float* x  = (const float*)d_in[0];
    const int*   ei = (const int*)d_in[1];   // int32 (JAX x64 disabled)
    const float* W1 = (const float*)d_in[2];
    const float* b1 = (const float*)d_in[3];
    const float* W2 = (const float*)d_in[4];
    const float* b2 = (const float*)d_in[5];
    float*       out = (float*)d_out;

    const int TB = 256;
    k_init_deg <<<(N_NODES + TB - 1) / TB, TB>>>();
    k_count_deg<<<(N_EDGES + TB - 1) / TB, TB>>>(ei);
    k_dinv     <<<(N_NODES + TB - 1) / TB, TB>>>();
    // gemm1 4th: the fixed-index ncu capture profiles it.
    k_gemm1    <<<(N_NODES + 255) / 256, 256>>>(x, W1);
    k_scan1    <<<N_SCANB, SCAN_B>>>();
    k_scan2    <<<1, 256>>>();
    k_scan3    <<<(N_NODES + TB - 1) / TB, TB>>>();
    k_sort     <<<(N_EDGES + TB - 1) / TB, TB>>>(ei);

    k_agg1     <<<(N_NODES * 32 + TB - 1) / TB, TB>>>();   // warp per node
    k_gemm2    <<<(N_NODES + 255) / 256, 256>>>(W2, b1);
    k_agg2     <<<(N_NODES * 32 + TB - 1) / TB, TB>>>(out, b2);
}

// round 10
// speedup vs baseline: 1.0859x; 1.0859x over previous
#include <cuda_runtime.h>
#include <cuda_fp16.h>
#include <mma.h>
using namespace nvcuda;

#define N_NODES 100000
#define N_EDGES 3200000
#define F_IN    256
#define F_HID   64
#define F_OUT   40
#define SCAN_B  512
#define N_SCANB ((N_NODES + SCAN_B - 1) / SCAN_B)   // 196

// ---------------- scratch (device globals: alloc-free) ----------------
__device__ int     g_dege  [N_NODES];
__device__ float   g_dinv  [N_NODES];
__device__ int     g_rowptr[N_NODES];
__device__ int     g_cursor[N_NODES];
__device__ int     g_bsum  [256];
__device__ int2    g_edges [N_EDGES];      // dst-sorted: {src, norm bits}
__device__ __half  g_xh  [(size_t)N_NODES * F_IN];  // x in fp16 (51.2MB)
__device__ __half  g_w1h [F_IN * F_HID];            // W1 in fp16
__device__ __half2 g_h   [N_NODES * 32];   // h1, fp16 pairs (64 feats)
__device__ float   g_agg1[N_NODES * 64];   // fp32 aggregation
__device__ __half2 g_h2  [N_NODES * 20];   // h2, fp16 pairs (40 feats)

// ---------------- fp16 converts ----------------
__global__ void k_convx(const float* __restrict__ x) {
    size_t i = (size_t)blockIdx.x * blockDim.x + threadIdx.x;   // one uint4 = 8 halfs
    if (i >= (size_t)N_NODES * F_IN / 8) return;
    const float4* src = (const float4*)x + i * 2;
    float4 a = src[0], b = src[1];
    __half2 h[4] = { __floats2half2_rn(a.x, a.y), __floats2half2_rn(a.z, a.w),
                     __floats2half2_rn(b.x, b.y), __floats2half2_rn(b.z, b.w) };
    ((uint4*)g_xh)[i] = *(uint4*)h;
}

__global__ void k_convw(const float* __restrict__ W1) {
    int i = blockIdx.x * blockDim.x + threadIdx.x;              // one uint4 = 8 halfs
    if (i >= F_IN * F_HID / 8) return;
    const float4* src = (const float4*)W1 + i * 2;
    float4 a = src[0], b = src[1];
    __half2 h[4] = { __floats2half2_rn(a.x, a.y), __floats2half2_rn(a.z, a.w),
                     __floats2half2_rn(b.x, b.y), __floats2half2_rn(b.z, b.w) };
    ((uint4*)g_w1h)[i] = *(uint4*)h;
}

// ---------------- degree / norm prep ----------------
__global__ void k_init_deg() {
    int n = blockIdx.x * blockDim.x + threadIdx.x;
    if (n < N_NODES) g_dege[n] = 0;
}

__global__ void k_count_deg(const int* __restrict__ ei) {
    int e = blockIdx.x * blockDim.x + threadIdx.x;
    if (e < N_EDGES) atomicAdd(&g_dege[__ldg(&ei[N_EDGES + e])], 1);
}

__global__ void k_dinv() {
    int n = blockIdx.x * blockDim.x + threadIdx.x;
    if (n < N_NODES) g_dinv[n] = rsqrtf((float)(g_dege[n] + 1));
}

// ---------------- exclusive scan of g_dege -> g_rowptr ----------------
__global__ __launch_bounds__(SCAN_B) void k_scan1() {
    __shared__ int sm[SCAN_B];
    int t = threadIdx.x;
    int i = blockIdx.x * SCAN_B + t;
    int v = (i < N_NODES) ? g_dege[i] : 0;
    sm[t] = v;
    __syncthreads();
    for (int o = 1; o < SCAN_B; o <<= 1) {
        int x = (t >= o) ? sm[t - o] : 0;
        __syncthreads();
        sm[t] += x;
        __syncthreads();
    }
    if (i < N_NODES) g_rowptr[i] = sm[t] - v;
    if (t == SCAN_B - 1) g_bsum[blockIdx.x] = sm[t];
}

__global__ __launch_bounds__(256) void k_scan2() {
    __shared__ int sm[256];
    int t = threadIdx.x;
    int v = (t < N_SCANB) ? g_bsum[t] : 0;
    sm[t] = v;
    __syncthreads();
    for (int o = 1; o < 256; o <<= 1) {
        int x = (t >= o) ? sm[t - o] : 0;
        __syncthreads();
        sm[t] += x;
        __syncthreads();
    }
    g_bsum[t] = sm[t] - v;
}

__global__ void k_scan3() {
    int i = blockIdx.x * blockDim.x + threadIdx.x;
    if (i < N_NODES) {
        int r = g_rowptr[i] + g_bsum[i / SCAN_B];
        g_rowptr[i] = r;
        g_cursor[i] = r;
    }
}

__global__ void k_sort(const int* __restrict__ ei) {
    int e = blockIdx.x * blockDim.x + threadIdx.x;
    if (e < N_EDGES) {
        int s = __ldg(&ei[e]);
        int d = __ldg(&ei[N_EDGES + e]);
        float nm = g_dinv[s] * g_dinv[d];
        int pos = atomicAdd(&g_cursor[d], 1);
        g_edges[pos] = make_int2(s, __float_as_int(nm));
    }
}

// ------- GEMM1 via tensor cores: h = x @ W1, fp16 in, fp32 acc, fp16 out -------
// 128 nodes/block, 8 warps; warp w owns node strip [w*16, +16) x all 64 cols.
// K chunked by 64: stage x[128][64] (smem stride 72) + W1[64][64]; 4x4 wmma steps.
#define XS_LD 72
__global__ __launch_bounds__(256) void k_gemm1_tc() {
    __shared__ __align__(16) char sraw[33024];
    __half* ws = (__half*)sraw;                 // [64][64]  8KB  (per K-chunk W1)
    __half* xs = (__half*)(sraw + 8192);        // [128][72] 18KB (x chunk, padded)
    float*  fb = (float*)sraw;                  // [8][16][64] 32KB (aliased, used after)

    int tid  = threadIdx.x;
    int warp = tid >> 5;
    int lane = tid & 31;
    int nodebase = blockIdx.x * 128;

    wmma::fragment<wmma::accumulator, 16, 16, 16, float> c[4];
#pragma unroll
    for (int ct = 0; ct < 4; ct++) wmma::fill_fragment(c[ct], 0.f);

#pragma unroll 1
    for (int kb = 0; kb < 4; kb++) {
        // stage W1 chunk: rows kb*64..+64, 64 cols. 4096 halfs = 512 uint4.
#pragma unroll
        for (int i = 0; i < 2; i++) {
            int u = tid + i * 256;              // uint4 index; row = u/8
            ((uint4*)ws)[u] = ((const uint4*)g_w1h)[(kb * 64) * 8 + u];
        }
        // stage x chunk: 128 rows x 64 halfs = 1024 uint4, row r = u/8
#pragma unroll
        for (int i = 0; i < 4; i++) {
            int u = tid + i * 256;
            int r = u >> 3, cc = u & 7;
            int node = nodebase + r;
            uint4 v = make_uint4(0u, 0u, 0u, 0u);
            if (node < N_NODES)
                v = *(const uint4*)(g_xh + (size_t)node * F_IN + kb * 64 + cc * 8);
            *(uint4*)(xs + r * XS_LD + cc * 8) = v;
        }
        __syncthreads();

#pragma unroll
        for (int kt = 0; kt < 4; kt++) {
            wmma::fragment<wmma::matrix_a, 16, 16, 16, __half, wmma::row_major> a;
            wmma::load_matrix_sync(a, xs + warp * 16 * XS_LD + kt * 16, XS_LD);
#pragma unroll
            for (int ct = 0; ct < 4; ct++) {
                wmma::fragment<wmma::matrix_b, 16, 16, 16, __half, wmma::row_major> b;
                wmma::load_matrix_sync(b, ws + kt * 16 * 64 + ct * 16, 64);
                wmma::mma_sync(c[ct], a, b, c[ct]);
            }
        }
        __syncthreads();
    }

    // write back: stage fp32 tiles to (aliased) smem, convert to half2 rows
    float* myfb = fb + warp * 16 * 64;
#pragma unroll
    for (int ct = 0; ct < 4; ct++)
        wmma::store_matrix_sync(myfb + ct * 16, c[ct], 64, wmma::mem_row_major);
    __syncwarp();

    int row = lane >> 1;                         // 16 rows per warp
    int ph  = lane & 1;                          // which 32-col half
    int node = nodebase + warp * 16 + row;
    if (node < N_NODES) {
        const float* fr = myfb + row * 64 + ph * 32;
        __half2* o = &g_h[(size_t)node * 32 + ph * 16];
#pragma unroll
        for (int j = 0; j < 16; j++)
            o[j] = __floats2half2_rn(fr[2 * j], fr[2 * j + 1]);
    }
}

// ------- layer-1 aggregation: warp/node, batch-8 MLP on full groups + tail -------
__global__ __launch_bounds__(256) void k_agg1() {
    int node = (blockIdx.x * 256 + threadIdx.x) >> 5;
    int lane = threadIdx.x & 31;
    if (node >= N_NODES) return;

    float dv = g_dinv[node];
    float s2 = dv * dv;
    float2 self = __half22float2(g_h[node * 32 + lane]);
    float a0 = s2 * self.x;
    float a1 = s2 * self.y;

    int start = g_rowptr[node];
    int cnt   = g_dege[node];
    for (int base = 0; base < cnt; base += 32) {
        int idx = base + lane;
        int2 rec = (idx < cnt) ? g_edges[start + idx] : make_int2(0, 0);
        int m = min(32, cnt - base);
        int j = 0;
        for (; j + 8 <= m; j += 8) {
            float  nms[8];
            float2 fv [8];
#pragma unroll
            for (int u = 0; u < 8; u++) {
                int src = __shfl_sync(0xFFFFFFFFu, rec.x, j + u);
                nms[u]  = __int_as_float(__shfl_sync(0xFFFFFFFFu, rec.y, j + u));
                fv[u]   = __half22float2(g_h[src * 32 + lane]);
            }
#pragma unroll
            for (int u = 0; u < 8; u++) { a0 += nms[u] * fv[u].x; a1 += nms[u] * fv[u].y; }
        }
        for (; j < m; j++) {
            int   src = __shfl_sync(0xFFFFFFFFu, rec.x, j);
            float nm  = __int_as_float(__shfl_sync(0xFFFFFFFFu, rec.y, j));
            float2 f = __half22float2(g_h[src * 32 + lane]);
            a0 += nm * f.x;
            a1 += nm * f.y;
        }
    }
    ((float2*)&g_agg1[node * 64])[lane] = make_float2(a0, a1);
}

// ---------------- GEMM2: h2 = relu(agg1 + b1) @ W2, fp16 out ----------------
__global__ __launch_bounds__(256) void k_gemm2(const float* __restrict__ W2,
                                               const float* __restrict__ b1) {
    __shared__ float w[64 * 40];
    __shared__ float bs[64];
    int node = blockIdx.x * 256 + threadIdx.x;

    const float4* wsrc = (const float4*)W2;
    float4* wdst = (float4*)w;
    for (int i = threadIdx.x; i < 64 * 10; i += 256) wdst[i] = wsrc[i];
    if (threadIdx.x < 64) bs[threadIdx.x] = b1[threadIdx.x];
    __syncthreads();

    if (node >= N_NODES) return;

    float acc[40];
#pragma unroll
    for (int j = 0; j < 40; j++) acc[j] = 0.f;

    const float4* ar = (const float4*)&g_agg1[node * 64];
#pragma unroll 4
    for (int k4 = 0; k4 < 16; k4++) {
        float4 a = ar[k4];
#pragma unroll
        for (int kk = 0; kk < 4; kk++) {
            int k = k4 * 4 + kk;
            float av = (kk == 0) ? a.x : (kk == 1) ? a.y : (kk == 2) ? a.z : a.w;
            float v = fmaxf(av + bs[k], 0.f);
            const float4* wr = (const float4*)(w + k * 40);
#pragma unroll
            for (int j = 0; j < 10; j++) {
                float4 wv = wr[j];
                acc[4 * j + 0] += v * wv.x;
                acc[4 * j + 1] += v * wv.y;
                acc[4 * j + 2] += v * wv.z;
                acc[4 * j + 3] += v * wv.w;
            }
        }
    }

    __half2* out = &g_h2[node * 20];
#pragma unroll
    for (int j = 0; j < 20; j++)
        out[j] = __floats2half2_rn(acc[2 * j], acc[2 * j + 1]);
}

// -- layer-2 aggregation + b2 + log-softmax fused: warp/node, batch-8 + tail --
__global__ __launch_bounds__(256) void k_agg2(float* __restrict__ out,
                                              const float* __restrict__ b2) {
    int node = (blockIdx.x * 256 + threadIdx.x) >> 5;
    int lane = threadIdx.x & 31;
    if (node >= N_NODES) return;

    float dv = g_dinv[node];
    float s2 = dv * dv;
    float a0 = 0.f, a1 = 0.f;
    if (lane < 20) {
        float2 self = __half22float2(g_h2[node * 20 + lane]);
        a0 = s2 * self.x;
        a1 = s2 * self.y;
    }

    int start = g_rowptr[node];
    int cnt   = g_dege[node];
    for (int base = 0; base < cnt; base += 32) {
        int idx = base + lane;
        int2 rec = (idx < cnt) ? g_edges[start + idx] : make_int2(0, 0);
        int m = min(32, cnt - base);
        int j = 0;
        for (; j + 8 <= m; j += 8) {
            float  nms[8];
            float2 fv [8];
#pragma unroll
            for (int u = 0; u < 8; u++) {
                int src = __shfl_sync(0xFFFFFFFFu, rec.x, j + u);
                nms[u]  = __int_as_float(__shfl_sync(0xFFFFFFFFu, rec.y, j + u));
                fv[u]   = (lane < 20) ? __half22float2(g_h2[src * 20 + lane])
                                      : make_float2(0.f, 0.f);
            }
#pragma unroll
            for (int u = 0; u < 8; u++) { a0 += nms[u] * fv[u].x; a1 += nms[u] * fv[u].y; }
        }
        for (; j < m; j++) {
            int   src = __shfl_sync(0xFFFFFFFFu, rec.x, j);
            float nm  = __int_as_float(__shfl_sync(0xFFFFFFFFu, rec.y, j));
            if (lane < 20) {
                float2 f = __half22float2(g_h2[src * 20 + lane]);
                a0 += nm * f.x;
                a1 += nm * f.y;
            }
        }
    }

    float v0 = -3.4e38f, v1 = -3.4e38f;
    if (lane < 20) {
        v0 = a0 + __ldg(&b2[2 * lane]);
        v1 = a1 + __ldg(&b2[2 * lane + 1]);
    }

    float mx = fmaxf(v0, v1);
#pragma unroll
    for (int o = 16; o > 0; o >>= 1)
        mx = fmaxf(mx, __shfl_xor_sync(0xFFFFFFFFu, mx, o));

    float s = (lane < 20) ? (expf(v0 - mx) + expf(v1 - mx)) : 0.f;
#pragma unroll
    for (int o = 16; o > 0; o >>= 1)
        s += __shfl_xor_sync(0xFFFFFFFFu, s, o);

    float ls = logf(s);
    if (lane < 20)
        ((float2*)(out + (size_t)node * 40))[lane] = make_float2(v0 - mx - ls, v1 - mx - ls);
}

// ---------------- launch ----------------
extern "C" void kernel_launch(void* const* d_in, const int* in_sizes, int n_in,
                              void* d_out, int out_size) {
    const float* x  = (const float*)d_in[0];
    const int*   ei = (const int*)d_in[1];   // int32 (JAX x64 disabled)
    const float* W1 = (const float*)d_in[2];
    const float* b1 = (const float*)d_in[3];
    const float* W2 = (const float*)d_in[4];
    const float* b2 = (const float*)d_in[5];
    float*       out = (float*)d_out;

    const int TB = 256;
    k_init_deg <<<(N_NODES + TB - 1) / TB, TB>>>();
    k_convw    <<<(F_IN * F_HID / 8 + TB - 1) / TB, TB>>>(W1);
    k_convx    <<<(int)(((size_t)N_NODES * F_IN / 8 + TB - 1) / TB), TB>>>(x);
    // 4th launch = ncu capture slot: the tensor-core GEMM
    k_gemm1_tc <<<(N_NODES + 127) / 128, 256>>>();
    k_count_deg<<<(N_EDGES + TB - 1) / TB, TB>>>(ei);
    k_dinv     <<<(N_NODES + TB - 1) / TB, TB>>>();
    k_scan1    <<<N_SCANB, SCAN_B>>>();
    k_scan2    <<<1, 256>>>();
    k_scan3    <<<(N_NODES + TB - 1) / TB, TB>>>();
    k_sort     <<<(N_EDGES + TB - 1) / TB, TB>>>(ei);

    k_agg1     <<<(N_NODES * 32 + TB - 1) / TB, TB>>>();   // warp per node
    k_gemm2    <<<(N_NODES + 255) / 256, 256>>>(W2, b1);
    k_agg2     <<<(N_NODES * 32 + TB - 1) / TB, TB>>>(out, b2);
}

// round 11
// speedup vs baseline: 1.2167x; 1.1204x over previous
#include <cuda_runtime.h>
#include <cuda_fp16.h>
#include <mma.h>
using namespace nvcuda;

#define N_NODES 100000
#define N_EDGES 3200000
#define F_IN    256
#define F_HID   64
#define F_OUT   40
#define SCAN_B  512
#define N_SCANB ((N_NODES + SCAN_B - 1) / SCAN_B)   // 196

// ---------------- scratch (device globals: alloc-free) ----------------
__device__ int     g_dege  [N_NODES];
__device__ float   g_dinv  [N_NODES];
__device__ int     g_rowptr[N_NODES];
__device__ int     g_cursor[N_NODES];
__device__ int     g_bsum  [256];
__device__ int2    g_edges [N_EDGES];      // dst-sorted: {src, norm bits}
__device__ __half  g_xh  [(size_t)N_NODES * F_IN];  // x in fp16 (51.2MB)
__device__ __half  g_w1h [F_IN * F_HID];            // W1 in fp16
__device__ __half2 g_h   [N_NODES * 32];   // h1, fp16 pairs (64 feats)
__device__ float   g_agg1[N_NODES * 64];   // fp32 aggregation
__device__ __half2 g_h2  [N_NODES * 20];   // h2, fp16 pairs (40 feats)

// ---------------- fp16 converts ----------------
__global__ void k_convx(const float* __restrict__ x) {
    size_t i = (size_t)blockIdx.x * blockDim.x + threadIdx.x;   // one uint4 = 8 halfs
    if (i >= (size_t)N_NODES * F_IN / 8) return;
    const float4* src = (const float4*)x + i * 2;
    float4 a = src[0], b = src[1];
    __half2 h[4] = { __floats2half2_rn(a.x, a.y), __floats2half2_rn(a.z, a.w),
                     __floats2half2_rn(b.x, b.y), __floats2half2_rn(b.z, b.w) };
    ((uint4*)g_xh)[i] = *(uint4*)h;
}

__global__ void k_convw(const float* __restrict__ W1) {
    int i = blockIdx.x * blockDim.x + threadIdx.x;              // one uint4 = 8 halfs
    if (i >= F_IN * F_HID / 8) return;
    const float4* src = (const float4*)W1 + i * 2;
    float4 a = src[0], b = src[1];
    __half2 h[4] = { __floats2half2_rn(a.x, a.y), __floats2half2_rn(a.z, a.w),
                     __floats2half2_rn(b.x, b.y), __floats2half2_rn(b.z, b.w) };
    ((uint4*)g_w1h)[i] = *(uint4*)h;
}

// ---------------- degree / norm prep ----------------
__global__ void k_init_deg() {
    int n = blockIdx.x * blockDim.x + threadIdx.x;
    if (n < N_NODES) g_dege[n] = 0;
}

__global__ void k_count_deg(const int* __restrict__ ei) {
    int e = blockIdx.x * blockDim.x + threadIdx.x;
    if (e < N_EDGES) atomicAdd(&g_dege[__ldg(&ei[N_EDGES + e])], 1);
}

__global__ void k_dinv() {
    int n = blockIdx.x * blockDim.x + threadIdx.x;
    if (n < N_NODES) g_dinv[n] = rsqrtf((float)(g_dege[n] + 1));
}

// ---------------- exclusive scan of g_dege -> g_rowptr ----------------
__global__ __launch_bounds__(SCAN_B) void k_scan1() {
    __shared__ int sm[SCAN_B];
    int t = threadIdx.x;
    int i = blockIdx.x * SCAN_B + t;
    int v = (i < N_NODES) ? g_dege[i] : 0;
    sm[t] = v;
    __syncthreads();
    for (int o = 1; o < SCAN_B; o <<= 1) {
        int x = (t >= o) ? sm[t - o] : 0;
        __syncthreads();
        sm[t] += x;
        __syncthreads();
    }
    if (i < N_NODES) g_rowptr[i] = sm[t] - v;
    if (t == SCAN_B - 1) g_bsum[blockIdx.x] = sm[t];
}

__global__ __launch_bounds__(256) void k_scan2() {
    __shared__ int sm[256];
    int t = threadIdx.x;
    int v = (t < N_SCANB) ? g_bsum[t] : 0;
    sm[t] = v;
    __syncthreads();
    for (int o = 1; o < 256; o <<= 1) {
        int x = (t >= o) ? sm[t - o] : 0;
        __syncthreads();
        sm[t] += x;
        __syncthreads();
    }
    g_bsum[t] = sm[t] - v;
}

__global__ void k_scan3() {
    int i = blockIdx.x * blockDim.x + threadIdx.x;
    if (i < N_NODES) {
        int r = g_rowptr[i] + g_bsum[i / SCAN_B];
        g_rowptr[i] = r;
        g_cursor[i] = r;
    }
}

__global__ void k_sort(const int* __restrict__ ei) {
    int e = blockIdx.x * blockDim.x + threadIdx.x;
    if (e < N_EDGES) {
        int s = __ldg(&ei[e]);
        int d = __ldg(&ei[N_EDGES + e]);
        float nm = g_dinv[s] * g_dinv[d];
        int pos = atomicAdd(&g_cursor[d], 1);
        g_edges[pos] = make_int2(s, __float_as_int(nm));
    }
}

// ------- GEMM1 via tensor cores: h = x @ W1, fp16 in, fp32 acc, fp16 out -------
// 256 nodes/block, 8 warps; warp w owns nodes [w*32, +32) (2 m-tiles) x all 64 cols.
// Both xs AND ws padded to stride 72 (conflict-free ldmatrix). Each B-fragment
// load feeds 2 MMAs (2 m-tiles).
#define XS_LD 72
__global__ __launch_bounds__(256) void k_gemm1_tc() {
    __shared__ __align__(16) char sraw[46080];
    __half* ws = (__half*)sraw;                 // [64][72]  9216B (per K-chunk W1)
    __half* xs = (__half*)(sraw + 9216);        // [256][72] 36864B (x chunk)
    float*  fb = (float*)sraw;                  // 8 warps x 16 x 64 f32 = 32KB (aliased)

    int tid  = threadIdx.x;
    int warp = tid >> 5;
    int lane = tid & 31;
    int nodebase = blockIdx.x * 256;

    wmma::fragment<wmma::accumulator, 16, 16, 16, float> c[2][4];
#pragma unroll
    for (int p = 0; p < 2; p++)
#pragma unroll
        for (int ct = 0; ct < 4; ct++) wmma::fill_fragment(c[p][ct], 0.f);

#pragma unroll 1
    for (int kb = 0; kb < 4; kb++) {
        // stage W1 chunk: rows kb*64..+64, 64 cols -> ws stride 72. 512 uint4.
#pragma unroll
        for (int i = 0; i < 2; i++) {
            int u = tid + i * 256;
            int r = u >> 3, cc = u & 7;
            uint4 v = ((const uint4*)g_w1h)[(kb * 64 + r) * 8 + cc];
            *(uint4*)(ws + r * XS_LD + cc * 8) = v;
        }
        // stage x chunk: 256 rows x 64 halfs -> xs stride 72. 2048 uint4.
#pragma unroll
        for (int i = 0; i < 8; i++) {
            int u = tid + i * 256;
            int r = u >> 3, cc = u & 7;
            int node = nodebase + r;
            uint4 v = make_uint4(0u, 0u, 0u, 0u);
            if (node < N_NODES)
                v = *(const uint4*)(g_xh + (size_t)node * F_IN + kb * 64 + cc * 8);
            *(uint4*)(xs + r * XS_LD + cc * 8) = v;
        }
        __syncthreads();

#pragma unroll
        for (int kt = 0; kt < 4; kt++) {
            wmma::fragment<wmma::matrix_a, 16, 16, 16, __half, wmma::row_major> a0, a1;
            wmma::load_matrix_sync(a0, xs + (warp * 32 +  0) * XS_LD + kt * 16, XS_LD);
            wmma::load_matrix_sync(a1, xs + (warp * 32 + 16) * XS_LD + kt * 16, XS_LD);
#pragma unroll
            for (int ct = 0; ct < 4; ct++) {
                wmma::fragment<wmma::matrix_b, 16, 16, 16, __half, wmma::row_major> b;
                wmma::load_matrix_sync(b, ws + kt * 16 * XS_LD + ct * 16, XS_LD);
                wmma::mma_sync(c[0][ct], a0, b, c[0][ct]);
                wmma::mma_sync(c[1][ct], a1, b, c[1][ct]);
            }
        }
        __syncthreads();   // ensures all mma done before xs reuse as fb (last iter)
    }

    // write back: per m-tile pass, stage fp32 to (aliased) smem, emit half2 rows
    float* myfb = fb + warp * 16 * 64;   // 8 warps x 4KB = 32KB
#pragma unroll
    for (int p = 0; p < 2; p++) {
#pragma unroll
        for (int ct = 0; ct < 4; ct++)
            wmma::store_matrix_sync(myfb + ct * 16, c[p][ct], 64, wmma::mem_row_major);
        __syncwarp();

        int row = lane >> 1;                     // 16 rows
        int ph  = lane & 1;                      // 32-col half
        int node = nodebase + warp * 32 + p * 16 + row;
        if (node < N_NODES) {
            const float* fr = myfb + row * 64 + ph * 32;
            __half2* o = &g_h[(size_t)node * 32 + ph * 16];
#pragma unroll
            for (int j = 0; j < 16; j++)
                o[j] = __floats2half2_rn(fr[2 * j], fr[2 * j + 1]);
        }
        __syncwarp();
    }
}

// ------- layer-1 aggregation: warp/node, batch-8 MLP on full groups + tail -------
__global__ __launch_bounds__(256) void k_agg1() {
    int node = (blockIdx.x * 256 + threadIdx.x) >> 5;
    int lane = threadIdx.x & 31;
    if (node >= N_NODES) return;

    float dv = g_dinv[node];
    float s2 = dv * dv;
    float2 self = __half22float2(g_h[node * 32 + lane]);
    float a0 = s2 * self.x;
    float a1 = s2 * self.y;

    int start = g_rowptr[node];
    int cnt   = g_dege[node];
    for (int base = 0; base < cnt; base += 32) {
        int idx = base + lane;
        int2 rec = (idx < cnt) ? g_edges[start + idx] : make_int2(0, 0);
        int m = min(32, cnt - base);
        int j = 0;
        for (; j + 8 <= m; j += 8) {
            float  nms[8];
            float2 fv [8];
#pragma unroll
            for (int u = 0; u < 8; u++) {
                int src = __shfl_sync(0xFFFFFFFFu, rec.x, j + u);
                nms[u]  = __int_as_float(__shfl_sync(0xFFFFFFFFu, rec.y, j + u));
                fv[u]   = __half22float2(g_h[src * 32 + lane]);
            }
#pragma unroll
            for (int u = 0; u < 8; u++) { a0 += nms[u] * fv[u].x; a1 += nms[u] * fv[u].y; }
        }
        for (; j < m; j++) {
            int   src = __shfl_sync(0xFFFFFFFFu, rec.x, j);
            float nm  = __int_as_float(__shfl_sync(0xFFFFFFFFu, rec.y, j));
            float2 f = __half22float2(g_h[src * 32 + lane]);
            a0 += nm * f.x;
            a1 += nm * f.y;
        }
    }
    ((float2*)&g_agg1[node * 64])[lane] = make_float2(a0, a1);
}

// ---------------- GEMM2: h2 = relu(agg1 + b1) @ W2, fp16 out ----------------
__global__ __launch_bounds__(256) void k_gemm2(const float* __restrict__ W2,
                                               const float* __restrict__ b1) {
    __shared__ float w[64 * 40];
    __shared__ float bs[64];
    int node = blockIdx.x * 256 + threadIdx.x;

    const float4* wsrc = (const float4*)W2;
    float4* wdst = (float4*)w;
    for (int i = threadIdx.x; i < 64 * 10; i += 256) wdst[i] = wsrc[i];
    if (threadIdx.x < 64) bs[threadIdx.x] = b1[threadIdx.x];
    __syncthreads();

    if (node >= N_NODES) return;

    float acc[40];
#pragma unroll
    for (int j = 0; j < 40; j++) acc[j] = 0.f;

    const float4* ar = (const float4*)&g_agg1[node * 64];
#pragma unroll 4
    for (int k4 = 0; k4 < 16; k4++) {
        float4 a = ar[k4];
#pragma unroll
        for (int kk = 0; kk < 4; kk++) {
            int k = k4 * 4 + kk;
            float av = (kk == 0) ? a.x : (kk == 1) ? a.y : (kk == 2) ? a.z : a.w;
            float v = fmaxf(av + bs[k], 0.f);
            const float4* wr = (const float4*)(w + k * 40);
#pragma unroll
            for (int j = 0; j < 10; j++) {
                float4 wv = wr[j];
                acc[4 * j + 0] += v * wv.x;
                acc[4 * j + 1] += v * wv.y;
                acc[4 * j + 2] += v * wv.z;
                acc[4 * j + 3] += v * wv.w;
            }
        }
    }

    __half2* out = &g_h2[node * 20];
#pragma unroll
    for (int j = 0; j < 20; j++)
        out[j] = __floats2half2_rn(acc[2 * j], acc[2 * j + 1]);
}

// -- layer-2 aggregation + b2 + log-softmax fused: warp/node, batch-8 + tail --
__global__ __launch_bounds__(256) void k_agg2(float* __restrict__ out,
                                              const float* __restrict__ b2) {
    int node = (blockIdx.x * 256 + threadIdx.x) >> 5;
    int lane = threadIdx.x & 31;
    if (node >= N_NODES) return;

    float dv = g_dinv[node];
    float s2 = dv * dv;
    float a0 = 0.f, a1 = 0.f;
    if (lane < 20) {
        float2 self = __half22float2(g_h2[node * 20 + lane]);
        a0 = s2 * self.x;
        a1 = s2 * self.y;
    }

    int start = g_rowptr[node];
    int cnt   = g_dege[node];
    for (int base = 0; base < cnt; base += 32) {
        int idx = base + lane;
        int2 rec = (idx < cnt) ? g_edges[start + idx] : make_int2(0, 0);
        int m = min(32, cnt - base);
        int j = 0;
        for (; j + 8 <= m; j += 8) {
            float  nms[8];
            float2 fv [8];
#pragma unroll
            for (int u = 0; u < 8; u++) {
                int src = __shfl_sync(0xFFFFFFFFu, rec.x, j + u);
                nms[u]  = __int_as_float(__shfl_sync(0xFFFFFFFFu, rec.y, j + u));
                fv[u]   = (lane < 20) ? __half22float2(g_h2[src * 20 + lane])
                                      : make_float2(0.f, 0.f);
            }
#pragma unroll
            for (int u = 0; u < 8; u++) { a0 += nms[u] * fv[u].x; a1 += nms[u] * fv[u].y; }
        }
        for (; j < m; j++) {
            int   src = __shfl_sync(0xFFFFFFFFu, rec.x, j);
            float nm  = __int_as_float(__shfl_sync(0xFFFFFFFFu, rec.y, j));
            if (lane < 20) {
                float2 f = __half22float2(g_h2[src * 20 + lane]);
                a0 += nm * f.x;
                a1 += nm * f.y;
            }
        }
    }

    float v0 = -3.4e38f, v1 = -3.4e38f;
    if (lane < 20) {
        v0 = a0 + __ldg(&b2[2 * lane]);
        v1 = a1 + __ldg(&b2[2 * lane + 1]);
    }

    float mx = fmaxf(v0, v1);
#pragma unroll
    for (int o = 16; o > 0; o >>= 1)
        mx = fmaxf(mx, __shfl_xor_sync(0xFFFFFFFFu, mx, o));

    float s = (lane < 20) ? (expf(v0 - mx) + expf(v1 - mx)) : 0.f;
#pragma unroll
    for (int o = 16; o > 0; o >>= 1)
        s += __shfl_xor_sync(0xFFFFFFFFu, s, o);

    float ls = logf(s);
    if (lane < 20)
        ((float2*)(out + (size_t)node * 40))[lane] = make_float2(v0 - mx - ls, v1 - mx - ls);
}

// ---------------- launch ----------------
extern "C" void kernel_launch(void* const* d_in, const int* in_sizes, int n_in,
                              void* d_out, int out_size) {
    const float* x  = (const float*)d_in[0];
    const int*   ei = (const int*)d_in[1];   // int32 (JAX x64 disabled)
    const float* W1 = (const float*)d_in[2];
    const float* b1 = (const float*)d_in[3];
    const float* W2 = (const float*)d_in[4];
    const float* b2 = (const float*)d_in[5];
    float*       out = (float*)d_out;

    const int TB = 256;
    k_init_deg <<<(N_NODES + TB - 1) / TB, TB>>>();
    k_convw    <<<(F_IN * F_HID / 8 + TB - 1) / TB, TB>>>(W1);
    k_convx    <<<(int)(((size_t)N_NODES * F_IN / 8 + TB - 1) / TB), TB>>>(x);
    // 4th launch = ncu capture slot: the tensor-core GEMM
    k_gemm1_tc <<<(N_NODES + 255) / 256, 256>>>();
    k_count_deg<<<(N_EDGES + TB - 1) / TB, TB>>>(ei);
    k_dinv     <<<(N_NODES + TB - 1) / TB, TB>>>();
    k_scan1    <<<N_SCANB, SCAN_B>>>();
    k_scan2    <<<1, 256>>>();
    k_scan3    <<<(N_NODES + TB - 1) / TB, TB>>>();
    k_sort     <<<(N_EDGES + TB - 1) / TB, TB>>>(ei);

    k_agg1     <<<(N_NODES * 32 + TB - 1) / TB, TB>>>();   // warp per node
    k_gemm2    <<<(N_NODES + 255) / 256, 256>>>(W2, b1);
    k_agg2     <<<(N_NODES * 32 + TB - 1) / TB, TB>>>(out, b2);
}

// round 12
// speedup vs baseline: 1.2381x; 1.0176x over previous
#include <cuda_runtime.h>
#include <cuda_fp16.h>
#include <mma.h>
using namespace nvcuda;

#define N_NODES 100000
#define N_EDGES 3200000
#define F_IN    256
#define F_HID   64
#define F_OUT   40
#define SCAN_B  512
#define N_SCANB ((N_NODES + SCAN_B - 1) / SCAN_B)   // 196

// ---------------- scratch (device globals: alloc-free) ----------------
__device__ int     g_dege  [N_NODES];
__device__ float   g_dinv  [N_NODES];
__device__ int     g_rowptr[N_NODES];
__device__ int     g_cursor[N_NODES];
__device__ int     g_bsum  [256];
__device__ int2    g_edges [N_EDGES];      // dst-sorted: {src, norm bits}
__device__ __half  g_xh  [(size_t)N_NODES * F_IN];  // x in fp16 (51.2MB)
__device__ __half  g_w1h [F_IN * F_HID];            // W1 in fp16
__device__ __half2 g_h   [N_NODES * 32];   // h1, fp16 pairs (64 feats, 128B rows)
__device__ float   g_agg1[N_NODES * 64];   // fp32 aggregation
__device__ __half2 g_h2  [N_NODES * 20];   // h2, fp16 pairs (40 feats, 80B rows)

// ---------------- fp16 converts ----------------
__global__ void k_convx(const float* __restrict__ x) {
    size_t i = (size_t)blockIdx.x * blockDim.x + threadIdx.x;   // one uint4 = 8 halfs
    if (i >= (size_t)N_NODES * F_IN / 8) return;
    const float4* src = (const float4*)x + i * 2;
    float4 a = src[0], b = src[1];
    __half2 h[4] = { __floats2half2_rn(a.x, a.y), __floats2half2_rn(a.z, a.w),
                     __floats2half2_rn(b.x, b.y), __floats2half2_rn(b.z, b.w) };
    ((uint4*)g_xh)[i] = *(uint4*)h;
}

__global__ void k_convw(const float* __restrict__ W1) {
    int i = blockIdx.x * blockDim.x + threadIdx.x;              // one uint4 = 8 halfs
    if (i >= F_IN * F_HID / 8) return;
    const float4* src = (const float4*)W1 + i * 2;
    float4 a = src[0], b = src[1];
    __half2 h[4] = { __floats2half2_rn(a.x, a.y), __floats2half2_rn(a.z, a.w),
                     __floats2half2_rn(b.x, b.y), __floats2half2_rn(b.z, b.w) };
    ((uint4*)g_w1h)[i] = *(uint4*)h;
}

// ---------------- degree / norm prep ----------------
__global__ void k_init_deg() {
    int n = blockIdx.x * blockDim.x + threadIdx.x;
    if (n < N_NODES) g_dege[n] = 0;
}

__global__ void k_count_deg(const int* __restrict__ ei) {
    int e = blockIdx.x * blockDim.x + threadIdx.x;
    if (e < N_EDGES) atomicAdd(&g_dege[__ldg(&ei[N_EDGES + e])], 1);
}

__global__ void k_dinv() {
    int n = blockIdx.x * blockDim.x + threadIdx.x;
    if (n < N_NODES) g_dinv[n] = rsqrtf((float)(g_dege[n] + 1));
}

// ---------------- exclusive scan of g_dege -> g_rowptr ----------------
__global__ __launch_bounds__(SCAN_B) void k_scan1() {
    __shared__ int sm[SCAN_B];
    int t = threadIdx.x;
    int i = blockIdx.x * SCAN_B + t;
    int v = (i < N_NODES) ? g_dege[i] : 0;
    sm[t] = v;
    __syncthreads();
    for (int o = 1; o < SCAN_B; o <<= 1) {
        int x = (t >= o) ? sm[t - o] : 0;
        __syncthreads();
        sm[t] += x;
        __syncthreads();
    }
    if (i < N_NODES) g_rowptr[i] = sm[t] - v;
    if (t == SCAN_B - 1) g_bsum[blockIdx.x] = sm[t];
}

__global__ __launch_bounds__(256) void k_scan2() {
    __shared__ int sm[256];
    int t = threadIdx.x;
    int v = (t < N_SCANB) ? g_bsum[t] : 0;
    sm[t] = v;
    __syncthreads();
    for (int o = 1; o < 256; o <<= 1) {
        int x = (t >= o) ? sm[t - o] : 0;
        __syncthreads();
        sm[t] += x;
        __syncthreads();
    }
    g_bsum[t] = sm[t] - v;
}

__global__ void k_scan3() {
    int i = blockIdx.x * blockDim.x + threadIdx.x;
    if (i < N_NODES) {
        int r = g_rowptr[i] + g_bsum[i / SCAN_B];
        g_rowptr[i] = r;
        g_cursor[i] = r;
    }
}

__global__ void k_sort(const int* __restrict__ ei) {
    int e = blockIdx.x * blockDim.x + threadIdx.x;
    if (e < N_EDGES) {
        int s = __ldg(&ei[e]);
        int d = __ldg(&ei[N_EDGES + e]);
        float nm = g_dinv[s] * g_dinv[d];
        int pos = atomicAdd(&g_cursor[d], 1);
        g_edges[pos] = make_int2(s, __float_as_int(nm));
    }
}

// ------- GEMM1 via tensor cores: h = x @ W1, fp16 in, fp32 acc, fp16 out -------
#define XS_LD 72
__global__ __launch_bounds__(256) void k_gemm1_tc() {
    __shared__ __align__(16) char sraw[46080];
    __half* ws = (__half*)sraw;                 // [64][72]  9216B
    __half* xs = (__half*)(sraw + 9216);        // [256][72] 36864B
    float*  fb = (float*)sraw;                  // aliased fp32 staging

    int tid  = threadIdx.x;
    int warp = tid >> 5;
    int lane = tid & 31;
    int nodebase = blockIdx.x * 256;

    wmma::fragment<wmma::accumulator, 16, 16, 16, float> c[2][4];
#pragma unroll
    for (int p = 0; p < 2; p++)
#pragma unroll
        for (int ct = 0; ct < 4; ct++) wmma::fill_fragment(c[p][ct], 0.f);

#pragma unroll 1
    for (int kb = 0; kb < 4; kb++) {
#pragma unroll
        for (int i = 0; i < 2; i++) {
            int u = tid + i * 256;
            int r = u >> 3, cc = u & 7;
            uint4 v = ((const uint4*)g_w1h)[(kb * 64 + r) * 8 + cc];
            *(uint4*)(ws + r * XS_LD + cc * 8) = v;
        }
#pragma unroll
        for (int i = 0; i < 8; i++) {
            int u = tid + i * 256;
            int r = u >> 3, cc = u & 7;
            int node = nodebase + r;
            uint4 v = make_uint4(0u, 0u, 0u, 0u);
            if (node < N_NODES)
                v = *(const uint4*)(g_xh + (size_t)node * F_IN + kb * 64 + cc * 8);
            *(uint4*)(xs + r * XS_LD + cc * 8) = v;
        }
        __syncthreads();

#pragma unroll
        for (int kt = 0; kt < 4; kt++) {
            wmma::fragment<wmma::matrix_a, 16, 16, 16, __half, wmma::row_major> a0, a1;
            wmma::load_matrix_sync(a0, xs + (warp * 32 +  0) * XS_LD + kt * 16, XS_LD);
            wmma::load_matrix_sync(a1, xs + (warp * 32 + 16) * XS_LD + kt * 16, XS_LD);
#pragma unroll
            for (int ct = 0; ct < 4; ct++) {
                wmma::fragment<wmma::matrix_b, 16, 16, 16, __half, wmma::row_major> b;
                wmma::load_matrix_sync(b, ws + kt * 16 * XS_LD + ct * 16, XS_LD);
                wmma::mma_sync(c[0][ct], a0, b, c[0][ct]);
                wmma::mma_sync(c[1][ct], a1, b, c[1][ct]);
            }
        }
        __syncthreads();
    }

    float* myfb = fb + warp * 16 * 64;
#pragma unroll
    for (int p = 0; p < 2; p++) {
#pragma unroll
        for (int ct = 0; ct < 4; ct++)
            wmma::store_matrix_sync(myfb + ct * 16, c[p][ct], 64, wmma::mem_row_major);
        __syncwarp();

        int row = lane >> 1;
        int ph  = lane & 1;
        int node = nodebase + warp * 32 + p * 16 + row;
        if (node < N_NODES) {
            const float* fr = myfb + row * 64 + ph * 32;
            __half2* o = &g_h[(size_t)node * 32 + ph * 16];
#pragma unroll
            for (int j = 0; j < 16; j++)
                o[j] = __floats2half2_rn(fr[2 * j], fr[2 * j + 1]);
        }
        __syncwarp();
    }
}

// ------- layer-1 aggregation: warp/node, 4 edges per warp-load -------
// 4 groups x 8 lanes; group g handles edge 4j+g of each 32-edge block; lane li
// loads uint4 #li of the edge's 128B feature row. Padded recs have norm=0 ->
// predicated load (no traffic). Per-lane fp32 acc covers features [li*8,+8);
// merge groups via shfl_xor(8,16).
__global__ __launch_bounds__(256) void k_agg1() {
    int node = (blockIdx.x * 256 + threadIdx.x) >> 5;
    int lane = threadIdx.x & 31;
    if (node >= N_NODES) return;
    int g  = lane >> 3;
    int li = lane & 7;

    float dv = g_dinv[node];
    float s2 = dv * dv;

    float acc[8];
    {   // self contribution (group 0 only; groups merged at the end)
        uint4 sv = *((const uint4*)(g_h + (size_t)node * 32) + li);
        __half2* hp = (__half2*)&sv;
        float m0 = (g == 0) ? s2 : 0.f;
#pragma unroll
        for (int t = 0; t < 4; t++) {
            float2 f = __half22float2(hp[t]);
            acc[2 * t]     = m0 * f.x;
            acc[2 * t + 1] = m0 * f.y;
        }
    }

    int start = g_rowptr[node];
    int cnt   = g_dege[node];
    for (int base = 0; base < cnt; base += 32) {
        int idx = base + lane;
        int2 rec = (idx < cnt) ? g_edges[start + idx] : make_int2(0, 0);
        float nm[8];
        uint4 v[8];
#pragma unroll
        for (int j = 0; j < 8; j++) {           // 8 batched predicated loads
            int sl  = 4 * j + g;
            int src = __shfl_sync(0xFFFFFFFFu, rec.x, sl);
            nm[j]   = __int_as_float(__shfl_sync(0xFFFFFFFFu, rec.y, sl));
            v[j] = make_uint4(0u, 0u, 0u, 0u);
            if (nm[j] != 0.f)
                v[j] = *((const uint4*)(g_h + (size_t)src * 32) + li);
        }
#pragma unroll
        for (int j = 0; j < 8; j++) {
            __half2* hp = (__half2*)&v[j];
#pragma unroll
            for (int t = 0; t < 4; t++) {
                float2 f = __half22float2(hp[t]);
                acc[2 * t]     += nm[j] * f.x;
                acc[2 * t + 1] += nm[j] * f.y;
            }
        }
    }

    // merge the 4 groups
#pragma unroll
    for (int k = 0; k < 8; k++) {
        acc[k] += __shfl_xor_sync(0xFFFFFFFFu, acc[k], 8);
        acc[k] += __shfl_xor_sync(0xFFFFFFFFu, acc[k], 16);
    }

    if (g == 0) {
        float4* o = (float4*)(g_agg1 + (size_t)node * 64 + li * 8);
        o[0] = make_float4(acc[0], acc[1], acc[2], acc[3]);
        o[1] = make_float4(acc[4], acc[5], acc[6], acc[7]);
    }
}

// ---------------- GEMM2: h2 = relu(agg1 + b1) @ W2, fp16 out ----------------
__global__ __launch_bounds__(256) void k_gemm2(const float* __restrict__ W2,
                                               const float* __restrict__ b1) {
    __shared__ float w[64 * 40];
    __shared__ float bs[64];
    int node = blockIdx.x * 256 + threadIdx.x;

    const float4* wsrc = (const float4*)W2;
    float4* wdst = (float4*)w;
    for (int i = threadIdx.x; i < 64 * 10; i += 256) wdst[i] = wsrc[i];
    if (threadIdx.x < 64) bs[threadIdx.x] = b1[threadIdx.x];
    __syncthreads();

    if (node >= N_NODES) return;

    float acc[40];
#pragma unroll
    for (int j = 0; j < 40; j++) acc[j] = 0.f;

    const float4* ar = (const float4*)&g_agg1[(size_t)node * 64];
#pragma unroll 4
    for (int k4 = 0; k4 < 16; k4++) {
        float4 a = ar[k4];
#pragma unroll
        for (int kk = 0; kk < 4; kk++) {
            int k = k4 * 4 + kk;
            float av = (kk == 0) ? a.x : (kk == 1) ? a.y : (kk == 2) ? a.z : a.w;
            float v = fmaxf(av + bs[k], 0.f);
            const float4* wr = (const float4*)(w + k * 40);
#pragma unroll
            for (int j = 0; j < 10; j++) {
                float4 wv = wr[j];
                acc[4 * j + 0] += v * wv.x;
                acc[4 * j + 1] += v * wv.y;
                acc[4 * j + 2] += v * wv.z;
                acc[4 * j + 3] += v * wv.w;
            }
        }
    }

    __half2* out = &g_h2[node * 20];
#pragma unroll
    for (int j = 0; j < 20; j++)
        out[j] = __floats2half2_rn(acc[2 * j], acc[2 * j + 1]);
}

// -- layer-2 aggregation + b2 + log-softmax: warp/node, 4 edges per warp-load --
// Rows are 40 halfs = 5 uint4: lanes li<5 of each group load/accumulate.
__global__ __launch_bounds__(256) void k_agg2(float* __restrict__ out,
                                              const float* __restrict__ b2) {
    int node = (blockIdx.x * 256 + threadIdx.x) >> 5;
    int lane = threadIdx.x & 31;
    if (node >= N_NODES) return;
    int g  = lane >> 3;
    int li = lane & 7;
    bool fvalid = (li < 5);

    float dv = g_dinv[node];
    float s2 = dv * dv;

    float acc[8];
    {
        uint4 sv = make_uint4(0u, 0u, 0u, 0u);
        if (fvalid) sv = *((const uint4*)(g_h2 + (size_t)node * 20) + li);
        __half2* hp = (__half2*)&sv;
        float m0 = (g == 0) ? s2 : 0.f;
#pragma unroll
        for (int t = 0; t < 4; t++) {
            float2 f = __half22float2(hp[t]);
            acc[2 * t]     = m0 * f.x;
            acc[2 * t + 1] = m0 * f.y;
        }
    }

    int start = g_rowptr[node];
    int cnt   = g_dege[node];
    for (int base = 0; base < cnt; base += 32) {
        int idx = base + lane;
        int2 rec = (idx < cnt) ? g_edges[start + idx] : make_int2(0, 0);
        float nm[8];
        uint4 v[8];
#pragma unroll
        for (int j = 0; j < 8; j++) {
            int sl  = 4 * j + g;
            int src = __shfl_sync(0xFFFFFFFFu, rec.x, sl);
            nm[j]   = __int_as_float(__shfl_sync(0xFFFFFFFFu, rec.y, sl));
            v[j] = make_uint4(0u, 0u, 0u, 0u);
            if (fvalid && nm[j] != 0.f)
                v[j] = *((const uint4*)(g_h2 + (size_t)src * 20) + li);
        }
#pragma unroll
        for (int j = 0; j < 8; j++) {
            __half2* hp = (__half2*)&v[j];
#pragma unroll
            for (int t = 0; t < 4; t++) {
                float2 f = __half22float2(hp[t]);
                acc[2 * t]     += nm[j] * f.x;
                acc[2 * t + 1] += nm[j] * f.y;
            }
        }
    }

#pragma unroll
    for (int k = 0; k < 8; k++) {
        acc[k] += __shfl_xor_sync(0xFFFFFFFFu, acc[k], 8);
        acc[k] += __shfl_xor_sync(0xFFFFFFFFu, acc[k], 16);
    }

    // + b2, then log-softmax over the 40 values held by (g==0, li<5)
    bool own = (g == 0) && fvalid;
    float vals[8];
    if (own) {
        float4 ba = ((const float4*)b2)[li * 2];
        float4 bb = ((const float4*)b2)[li * 2 + 1];
        vals[0] = acc[0] + ba.x; vals[1] = acc[1] + ba.y;
        vals[2] = acc[2] + ba.z; vals[3] = acc[3] + ba.w;
        vals[4] = acc[4] + bb.x; vals[5] = acc[5] + bb.y;
        vals[6] = acc[6] + bb.z; vals[7] = acc[7] + bb.w;
    } else {
#pragma unroll
        for (int k = 0; k < 8; k++) vals[k] = -3.4e38f;
    }

    float mx = vals[0];
#pragma unroll
    for (int k = 1; k < 8; k++) mx = fmaxf(mx, vals[k]);
#pragma unroll
    for (int o = 16; o > 0; o >>= 1)
        mx = fmaxf(mx, __shfl_xor_sync(0xFFFFFFFFu, mx, o));

    float s = 0.f;
    if (own) {
#pragma unroll
        for (int k = 0; k < 8; k++) s += expf(vals[k] - mx);
    }
#pragma unroll
    for (int o = 16; o > 0; o >>= 1)
        s += __shfl_xor_sync(0xFFFFFFFFu, s, o);

    float ls = logf(s) + mx;
    if (own) {
        float4* o0 = (float4*)(out + (size_t)node * 40 + li * 8);
        o0[0] = make_float4(vals[0] - ls, vals[1] - ls, vals[2] - ls, vals[3] - ls);
        o0[1] = make_float4(vals[4] - ls, vals[5] - ls, vals[6] - ls, vals[7] - ls);
    }
}

// ---------------- launch ----------------
extern "C" void kernel_launch(void* const* d_in, const int* in_sizes, int n_in,
                              void* d_out, int out_size) {
    const float* x  = (const float*)d_in[0];
    const int*   ei = (const int*)d_in[1];   // int32 (JAX x64 disabled)
    const float* W1 = (const float*)d_in[2];
    const float* b1 = (const float*)d_in[3];
    const float* W2 = (const float*)d_in[4];
    const float* b2 = (const float*)d_in[5];
    float*       out = (float*)d_out;

    const int TB = 256;
    k_init_deg <<<(N_NODES + TB - 1) / TB, TB>>>();
    k_convw    <<<(F_IN * F_HID / 8 + TB - 1) / TB, TB>>>(W1);
    k_convx    <<<(int)(((size_t)N_NODES * F_IN / 8 + TB - 1) / TB), TB>>>(x);
    // 4th launch = ncu capture slot
    k_gemm1_tc <<<(N_NODES + 255) / 256, 256>>>();
    k_count_deg<<<(N_EDGES + TB - 1) / TB, TB>>>(ei);
    k_dinv     <<<(N_NODES + TB - 1) / TB, TB>>>();
    k_scan1    <<<N_SCANB, SCAN_B>>>();
    k_scan2    <<<1, 256>>>();
    k_scan3    <<<(N_NODES + TB - 1) / TB, TB>>>();
    k_sort     <<<(N_EDGES + TB - 1) / TB, TB>>>(ei);

    k_agg1     <<<(N_NODES * 32 + TB - 1) / TB, TB>>>();   // warp per node
    k_gemm2    <<<(N_NODES + 255) / 256, 256>>>(W2, b1);
    k_agg2     <<<(N_NODES * 32 + TB - 1) / TB, TB>>>(out, b2);
}

// round 13
// speedup vs baseline: 1.3273x; 1.0721x over previous
#include <cuda_runtime.h>
#include <cuda_fp16.h>
#include <mma.h>
using namespace nvcuda;

#define N_NODES 100000
#define N_EDGES 3200000
#define F_IN    256
#define F_HID   64
#define F_OUT   40
#define SCAN_B  512
#define N_SCANB ((N_NODES + SCAN_B - 1) / SCAN_B)   // 196

// ---------------- scratch (device globals: alloc-free) ----------------
__device__ int     g_dege  [N_NODES];
__device__ float   g_dinv  [N_NODES];
__device__ int     g_rowptr[N_NODES];
__device__ int     g_cursor[N_NODES];
__device__ int     g_bsum  [256];
__device__ int2    g_edges [N_EDGES];      // dst-sorted: {src, norm bits}
__device__ __half  g_xh  [(size_t)N_NODES * F_IN];  // x in fp16
__device__ __half  g_w1h [F_IN * F_HID];            // W1 in fp16
__device__ __half  g_w2h [F_HID * 48];              // W2 in fp16, N padded 40->48
__device__ __half2 g_h   [N_NODES * 32];   // h1, fp16 (64 feats, 128B rows)
__device__ __half  g_hr  [(size_t)N_NODES * 64];    // relu(agg1+b1), fp16
__device__ __half2 g_h2  [N_NODES * 20];   // h2, fp16 (40 feats, 80B rows)

// ---------------- fp16 converts ----------------
__global__ void k_convx(const float* __restrict__ x) {
    size_t i = (size_t)blockIdx.x * blockDim.x + threadIdx.x;   // one uint4 = 8 halfs
    if (i >= (size_t)N_NODES * F_IN / 8) return;
    const float4* src = (const float4*)x + i * 2;
    float4 a = src[0], b = src[1];
    __half2 h[4] = { __floats2half2_rn(a.x, a.y), __floats2half2_rn(a.z, a.w),
                     __floats2half2_rn(b.x, b.y), __floats2half2_rn(b.z, b.w) };
    ((uint4*)g_xh)[i] = *(uint4*)h;
}

__global__ void k_convw(const float* __restrict__ W1) {
    int i = blockIdx.x * blockDim.x + threadIdx.x;
    if (i >= F_IN * F_HID / 8) return;
    const float4* src = (const float4*)W1 + i * 2;
    float4 a = src[0], b = src[1];
    __half2 h[4] = { __floats2half2_rn(a.x, a.y), __floats2half2_rn(a.z, a.w),
                     __floats2half2_rn(b.x, b.y), __floats2half2_rn(b.z, b.w) };
    ((uint4*)g_w1h)[i] = *(uint4*)h;
}

__global__ void k_convw2(const float* __restrict__ W2) {
    int i = blockIdx.x * blockDim.x + threadIdx.x;   // over 64*48
    if (i >= F_HID * 48) return;
    int r = i / 48, c = i % 48;
    g_w2h[i] = __float2half_rn((c < F_OUT) ? W2[r * F_OUT + c] : 0.f);
}

// ---------------- degree / norm prep ----------------
__global__ void k_init_deg() {
    int n = blockIdx.x * blockDim.x + threadIdx.x;
    if (n < N_NODES) g_dege[n] = 0;
}

__global__ void k_count_deg(const int* __restrict__ ei) {
    int e = blockIdx.x * blockDim.x + threadIdx.x;
    if (e < N_EDGES) atomicAdd(&g_dege[__ldg(&ei[N_EDGES + e])], 1);
}

__global__ void k_dinv() {
    int n = blockIdx.x * blockDim.x + threadIdx.x;
    if (n < N_NODES) g_dinv[n] = rsqrtf((float)(g_dege[n] + 1));
}

// ---------------- exclusive scan of g_dege -> g_rowptr ----------------
__global__ __launch_bounds__(SCAN_B) void k_scan1() {
    __shared__ int sm[SCAN_B];
    int t = threadIdx.x;
    int i = blockIdx.x * SCAN_B + t;
    int v = (i < N_NODES) ? g_dege[i] : 0;
    sm[t] = v;
    __syncthreads();
    for (int o = 1; o < SCAN_B; o <<= 1) {
        int x = (t >= o) ? sm[t - o] : 0;
        __syncthreads();
        sm[t] += x;
        __syncthreads();
    }
    if (i < N_NODES) g_rowptr[i] = sm[t] - v;
    if (t == SCAN_B - 1) g_bsum[blockIdx.x] = sm[t];
}

__global__ __launch_bounds__(256) void k_scan2() {
    __shared__ int sm[256];
    int t = threadIdx.x;
    int v = (t < N_SCANB) ? g_bsum[t] : 0;
    sm[t] = v;
    __syncthreads();
    for (int o = 1; o < 256; o <<= 1) {
        int x = (t >= o) ? sm[t - o] : 0;
        __syncthreads();
        sm[t] += x;
        __syncthreads();
    }
    g_bsum[t] = sm[t] - v;
}

__global__ void k_scan3() {
    int i = blockIdx.x * blockDim.x + threadIdx.x;
    if (i < N_NODES) {
        int r = g_rowptr[i] + g_bsum[i / SCAN_B];
        g_rowptr[i] = r;
        g_cursor[i] = r;
    }
}

__global__ void k_sort(const int* __restrict__ ei) {
    int e = blockIdx.x * blockDim.x + threadIdx.x;
    if (e < N_EDGES) {
        int s = __ldg(&ei[e]);
        int d = __ldg(&ei[N_EDGES + e]);
        float nm = g_dinv[s] * g_dinv[d];
        int pos = atomicAdd(&g_cursor[d], 1);
        g_edges[pos] = make_int2(s, __float_as_int(nm));
    }
}

// ------- GEMM1 via tensor cores: h = x @ W1, fp16 in, fp32 acc, fp16 out -------
#define XS_LD 72
__global__ __launch_bounds__(256) void k_gemm1_tc() {
    __shared__ __align__(16) char sraw[46080];
    __half* ws = (__half*)sraw;                 // [64][72]  9216B
    __half* xs = (__half*)(sraw + 9216);        // [256][72] 36864B
    float*  fb = (float*)sraw;                  // aliased fp32 staging

    int tid  = threadIdx.x;
    int warp = tid >> 5;
    int lane = tid & 31;
    int nodebase = blockIdx.x * 256;

    wmma::fragment<wmma::accumulator, 16, 16, 16, float> c[2][4];
#pragma unroll
    for (int p = 0; p < 2; p++)
#pragma unroll
        for (int ct = 0; ct < 4; ct++) wmma::fill_fragment(c[p][ct], 0.f);

#pragma unroll 1
    for (int kb = 0; kb < 4; kb++) {
#pragma unroll
        for (int i = 0; i < 2; i++) {
            int u = tid + i * 256;
            int r = u >> 3, cc = u & 7;
            uint4 v = ((const uint4*)g_w1h)[(kb * 64 + r) * 8 + cc];
            *(uint4*)(ws + r * XS_LD + cc * 8) = v;
        }
#pragma unroll
        for (int i = 0; i < 8; i++) {
            int u = tid + i * 256;
            int r = u >> 3, cc = u & 7;
            int node = nodebase + r;
            uint4 v = make_uint4(0u, 0u, 0u, 0u);
            if (node < N_NODES)
                v = *(const uint4*)(g_xh + (size_t)node * F_IN + kb * 64 + cc * 8);
            *(uint4*)(xs + r * XS_LD + cc * 8) = v;
        }
        __syncthreads();

#pragma unroll
        for (int kt = 0; kt < 4; kt++) {
            wmma::fragment<wmma::matrix_a, 16, 16, 16, __half, wmma::row_major> a0, a1;
            wmma::load_matrix_sync(a0, xs + (warp * 32 +  0) * XS_LD + kt * 16, XS_LD);
            wmma::load_matrix_sync(a1, xs + (warp * 32 + 16) * XS_LD + kt * 16, XS_LD);
#pragma unroll
            for (int ct = 0; ct < 4; ct++) {
                wmma::fragment<wmma::matrix_b, 16, 16, 16, __half, wmma::row_major> b;
                wmma::load_matrix_sync(b, ws + kt * 16 * XS_LD + ct * 16, XS_LD);
                wmma::mma_sync(c[0][ct], a0, b, c[0][ct]);
                wmma::mma_sync(c[1][ct], a1, b, c[1][ct]);
            }
        }
        __syncthreads();
    }

    float* myfb = fb + warp * 16 * 64;
#pragma unroll
    for (int p = 0; p < 2; p++) {
#pragma unroll
        for (int ct = 0; ct < 4; ct++)
            wmma::store_matrix_sync(myfb + ct * 16, c[p][ct], 64, wmma::mem_row_major);
        __syncwarp();

        int row = lane >> 1;
        int ph  = lane & 1;
        int node = nodebase + warp * 32 + p * 16 + row;
        if (node < N_NODES) {
            const float* fr = myfb + row * 64 + ph * 32;
            __half2* o = &g_h[(size_t)node * 32 + ph * 16];
#pragma unroll
            for (int j = 0; j < 16; j++)
                o[j] = __floats2half2_rn(fr[2 * j], fr[2 * j + 1]);
        }
        __syncwarp();
    }
}

// ------- layer-1 aggregation + bias + relu: warp/node, 4 edges per warp-load -----
// Emits fp16 relu(agg + b1) rows directly (input to tensor-core GEMM2).
__global__ __launch_bounds__(256) void k_agg1(const float* __restrict__ b1) {
    int node = (blockIdx.x * 256 + threadIdx.x) >> 5;
    int lane = threadIdx.x & 31;
    if (node >= N_NODES) return;
    int g  = lane >> 3;
    int li = lane & 7;

    float dv = g_dinv[node];
    float s2 = dv * dv;

    float acc[8];
    {   // self contribution (group 0 only; groups merged at the end)
        uint4 sv = *((const uint4*)(g_h + (size_t)node * 32) + li);
        __half2* hp = (__half2*)&sv;
        float m0 = (g == 0) ? s2 : 0.f;
#pragma unroll
        for (int t = 0; t < 4; t++) {
            float2 f = __half22float2(hp[t]);
            acc[2 * t]     = m0 * f.x;
            acc[2 * t + 1] = m0 * f.y;
        }
    }

    int start = g_rowptr[node];
    int cnt   = g_dege[node];
    for (int base = 0; base < cnt; base += 32) {
        int idx = base + lane;
        int2 rec = (idx < cnt) ? g_edges[start + idx] : make_int2(0, 0);
        float nm[8];
        uint4 v[8];
#pragma unroll
        for (int j = 0; j < 8; j++) {
            int sl  = 4 * j + g;
            int src = __shfl_sync(0xFFFFFFFFu, rec.x, sl);
            nm[j]   = __int_as_float(__shfl_sync(0xFFFFFFFFu, rec.y, sl));
            v[j] = make_uint4(0u, 0u, 0u, 0u);
            if (nm[j] != 0.f)
                v[j] = *((const uint4*)(g_h + (size_t)src * 32) + li);
        }
#pragma unroll
        for (int j = 0; j < 8; j++) {
            __half2* hp = (__half2*)&v[j];
#pragma unroll
            for (int t = 0; t < 4; t++) {
                float2 f = __half22float2(hp[t]);
                acc[2 * t]     += nm[j] * f.x;
                acc[2 * t + 1] += nm[j] * f.y;
            }
        }
    }

#pragma unroll
    for (int k = 0; k < 8; k++) {
        acc[k] += __shfl_xor_sync(0xFFFFFFFFu, acc[k], 8);
        acc[k] += __shfl_xor_sync(0xFFFFFFFFu, acc[k], 16);
    }

    if (g == 0) {
        float4 ba = ((const float4*)b1)[li * 2];
        float4 bb = ((const float4*)b1)[li * 2 + 1];
        __half2 h[4];
        h[0] = __floats2half2_rn(fmaxf(acc[0] + ba.x, 0.f), fmaxf(acc[1] + ba.y, 0.f));
        h[1] = __floats2half2_rn(fmaxf(acc[2] + ba.z, 0.f), fmaxf(acc[3] + ba.w, 0.f));
        h[2] = __floats2half2_rn(fmaxf(acc[4] + bb.x, 0.f), fmaxf(acc[5] + bb.y, 0.f));
        h[3] = __floats2half2_rn(fmaxf(acc[6] + bb.z, 0.f), fmaxf(acc[7] + bb.w, 0.f));
        *((uint4*)(g_hr + (size_t)node * 64) + li) = *(uint4*)h;
    }
}

// ------- GEMM2 via tensor cores: h2 = h_r @ W2, fp16 in, fp32 acc, fp16 out ------
// 256 nodes/block, warp = 32 nodes x 48 cols (3 n-tiles, cols 40..47 are zero pad).
__global__ __launch_bounds__(256) void k_gemm2_tc() {
    __shared__ __align__(16) char sraw[46080];
    __half* ws = (__half*)sraw;                 // [64][72]  9216B  (W2 padded)
    __half* hs = (__half*)(sraw + 9216);        // [256][72] 36864B (h_r tile)
    float*  fb = (float*)sraw;                  // aliased: 8 x 16x64 f32 = 32KB

    int tid  = threadIdx.x;
    int warp = tid >> 5;
    int lane = tid & 31;
    int nodebase = blockIdx.x * 256;

    // stage W2 [64][48] -> ws stride 72 (384 uint4)
    for (int u = tid; u < 384; u += 256) {
        int r = u / 6, c = u % 6;
        uint4 v = ((const uint4*)g_w2h)[u];
        *(uint4*)(ws + r * XS_LD + c * 8) = v;
    }
    // stage h_r tile: 256 rows x 64 halfs (2048 uint4)
#pragma unroll
    for (int i = 0; i < 8; i++) {
        int u = tid + i * 256;
        int r = u >> 3, c = u & 7;
        int node = nodebase + r;
        uint4 v = make_uint4(0u, 0u, 0u, 0u);
        if (node < N_NODES)
            v = *((const uint4*)(g_hr + (size_t)node * 64) + c);
        *(uint4*)(hs + r * XS_LD + c * 8) = v;
    }
    __syncthreads();

    wmma::fragment<wmma::accumulator, 16, 16, 16, float> c[2][3];
#pragma unroll
    for (int p = 0; p < 2; p++)
#pragma unroll
        for (int ct = 0; ct < 3; ct++) wmma::fill_fragment(c[p][ct], 0.f);

#pragma unroll
    for (int kt = 0; kt < 4; kt++) {
        wmma::fragment<wmma::matrix_a, 16, 16, 16, __half, wmma::row_major> a0, a1;
        wmma::load_matrix_sync(a0, hs + (warp * 32 +  0) * XS_LD + kt * 16, XS_LD);
        wmma::load_matrix_sync(a1, hs + (warp * 32 + 16) * XS_LD + kt * 16, XS_LD);
#pragma unroll
        for (int ct = 0; ct < 3; ct++) {
            wmma::fragment<wmma::matrix_b, 16, 16, 16, __half, wmma::row_major> b;
            wmma::load_matrix_sync(b, ws + kt * 16 * XS_LD + ct * 16, XS_LD);
            wmma::mma_sync(c[0][ct], a0, b, c[0][ct]);
            wmma::mma_sync(c[1][ct], a1, b, c[1][ct]);
        }
    }
    __syncthreads();   // all reads of ws/hs done before fb alias writes

    float* myfb = fb + warp * 16 * 64;
#pragma unroll
    for (int p = 0; p < 2; p++) {
#pragma unroll
        for (int ct = 0; ct < 3; ct++)
            wmma::store_matrix_sync(myfb + ct * 16, c[p][ct], 64, wmma::mem_row_major);
        __syncwarp();

        int row = lane >> 1;                    // 16 rows
        int ph  = lane & 1;                     // cols [0,20) or [20,40)
        int node = nodebase + warp * 32 + p * 16 + row;
        if (node < N_NODES) {
            const float* fr = myfb + row * 64 + ph * 20;
            __half2* o = &g_h2[(size_t)node * 20 + ph * 10];
#pragma unroll
            for (int j = 0; j < 10; j++)
                o[j] = __floats2half2_rn(fr[2 * j], fr[2 * j + 1]);
        }
        __syncwarp();
    }
}

// -- layer-2 aggregation + b2 + log-softmax: warp/node, 4 edges per warp-load --
__global__ __launch_bounds__(256) void k_agg2(float* __restrict__ out,
                                              const float* __restrict__ b2) {
    int node = (blockIdx.x * 256 + threadIdx.x) >> 5;
    int lane = threadIdx.x & 31;
    if (node >= N_NODES) return;
    int g  = lane >> 3;
    int li = lane & 7;
    bool fvalid = (li < 5);

    float dv = g_dinv[node];
    float s2 = dv * dv;

    float acc[8];
    {
        uint4 sv = make_uint4(0u, 0u, 0u, 0u);
        if (fvalid) sv = *((const uint4*)(g_h2 + (size_t)node * 20) + li);
        __half2* hp = (__half2*)&sv;
        float m0 = (g == 0) ? s2 : 0.f;
#pragma unroll
        for (int t = 0; t < 4; t++) {
            float2 f = __half22float2(hp[t]);
            acc[2 * t]     = m0 * f.x;
            acc[2 * t + 1] = m0 * f.y;
        }
    }

    int start = g_rowptr[node];
    int cnt   = g_dege[node];
    for (int base = 0; base < cnt; base += 32) {
        int idx = base + lane;
        int2 rec = (idx < cnt) ? g_edges[start + idx] : make_int2(0, 0);
        float nm[8];
        uint4 v[8];
#pragma unroll
        for (int j = 0; j < 8; j++) {
            int sl  = 4 * j + g;
            int src = __shfl_sync(0xFFFFFFFFu, rec.x, sl);
            nm[j]   = __int_as_float(__shfl_sync(0xFFFFFFFFu, rec.y, sl));
            v[j] = make_uint4(0u, 0u, 0u, 0u);
            if (fvalid && nm[j] != 0.f)
                v[j] = *((const uint4*)(g_h2 + (size_t)src * 20) + li);
        }
#pragma unroll
        for (int j = 0; j < 8; j++) {
            __half2* hp = (__half2*)&v[j];
#pragma unroll
            for (int t = 0; t < 4; t++) {
                float2 f = __half22float2(hp[t]);
                acc[2 * t]     += nm[j] * f.x;
                acc[2 * t + 1] += nm[j] * f.y;
            }
        }
    }

#pragma unroll
    for (int k = 0; k < 8; k++) {
        acc[k] += __shfl_xor_sync(0xFFFFFFFFu, acc[k], 8);
        acc[k] += __shfl_xor_sync(0xFFFFFFFFu, acc[k], 16);
    }

    bool own = (g == 0) && fvalid;
    float vals[8];
    if (own) {
        float4 ba = ((const float4*)b2)[li * 2];
        float4 bb = ((const float4*)b2)[li * 2 + 1];
        vals[0] = acc[0] + ba.x; vals[1] = acc[1] + ba.y;
        vals[2] = acc[2] + ba.z; vals[3] = acc[3] + ba.w;
        vals[4] = acc[4] + bb.x; vals[5] = acc[5] + bb.y;
        vals[6] = acc[6] + bb.z; vals[7] = acc[7] + bb.w;
    } else {
#pragma unroll
        for (int k = 0; k < 8; k++) vals[k] = -3.4e38f;
    }

    float mx = vals[0];
#pragma unroll
    for (int k = 1; k < 8; k++) mx = fmaxf(mx, vals[k]);
#pragma unroll
    for (int o = 16; o > 0; o >>= 1)
        mx = fmaxf(mx, __shfl_xor_sync(0xFFFFFFFFu, mx, o));

    float s = 0.f;
    if (own) {
#pragma unroll
        for (int k = 0; k < 8; k++) s += expf(vals[k] - mx);
    }
#pragma unroll
    for (int o = 16; o > 0; o >>= 1)
        s += __shfl_xor_sync(0xFFFFFFFFu, s, o);

    float ls = logf(s) + mx;
    if (own) {
        float4* o0 = (float4*)(out + (size_t)node * 40 + li * 8);
        o0[0] = make_float4(vals[0] - ls, vals[1] - ls, vals[2] - ls, vals[3] - ls);
        o0[1] = make_float4(vals[4] - ls, vals[5] - ls, vals[6] - ls, vals[7] - ls);
    }
}

// ---------------- launch ----------------
extern "C" void kernel_launch(void* const* d_in, const int* in_sizes, int n_in,
                              void* d_out, int out_size) {
    const float* x  = (const float*)d_in[0];
    const int*   ei = (const int*)d_in[1];   // int32 (JAX x64 disabled)
    const float* W1 = (const float*)d_in[2];
    const float* b1 = (const float*)d_in[3];
    const float* W2 = (const float*)d_in[4];
    const float* b2 = (const float*)d_in[5];
    float*       out = (float*)d_out;

    const int TB = 256;
    k_init_deg <<<(N_NODES + TB - 1) / TB, TB>>>();
    k_convw    <<<(F_IN * F_HID / 8 + TB - 1) / TB, TB>>>(W1);
    k_convx    <<<(int)(((size_t)N_NODES * F_IN / 8 + TB - 1) / TB), TB>>>(x);
    // 4th launch = ncu capture slot
    k_gemm1_tc <<<(N_NODES + 255) / 256, 256>>>();
    k_count_deg<<<(N_EDGES + TB - 1) / TB, TB>>>(ei);
    k_dinv     <<<(N_NODES + TB - 1) / TB, TB>>>();
    k_scan1    <<<N_SCANB, SCAN_B>>>();
    k_scan2    <<<1, 256>>>();
    k_scan3    <<<(N_NODES + TB - 1) / TB, TB>>>();
    k_sort     <<<(N_EDGES + TB - 1) / TB, TB>>>(ei);
    k_convw2   <<<(F_HID * 48 + TB - 1) / TB, TB>>>(W2);

    k_agg1     <<<(N_NODES * 32 + TB - 1) / TB, TB>>>(b1);
    k_gemm2_tc <<<(N_NODES + 255) / 256, 256>>>();
    k_agg2     <<<(N_NODES * 32 + TB - 1) / TB, TB>>>(out, b2);
}

// round 14
// speedup vs baseline: 1.3949x; 1.0510x over previous
#include <cuda_runtime.h>
#include <cuda_fp16.h>
#include <mma.h>
using namespace nvcuda;

#define N_NODES 100000
#define N_EDGES 3200000
#define F_IN    256
#define F_HID   64
#define F_OUT   40
#define SCAN_B  512
#define N_SCANB ((N_NODES + SCAN_B - 1) / SCAN_B)   // 196

// ---------------- scratch (device globals: alloc-free) ----------------
__device__ int     g_dege  [N_NODES];
__device__ float   g_dinv  [N_NODES];
__device__ int     g_rowptr[N_NODES];
__device__ int     g_cursor[N_NODES];
__device__ int     g_bsum  [256];
__device__ int     g_srcs  [N_EDGES];      // dst-sorted src ids (4B/edge)
__device__ __half  g_w1h [F_IN * F_HID];            // W1 fp16
__device__ __half  g_w2h [F_HID * 48];              // W2 fp16, N padded 40->48
__device__ __half2 g_h   [N_NODES * 32];   // h' = dinv*(x@W1), fp16, 128B rows
__device__ __half  g_hr  [(size_t)N_NODES * 64];    // relu(dinv*agg+b1), fp16
__device__ __half2 g_h2  [N_NODES * 20];   // h2' = dinv*(hr@W2), fp16, 80B rows

// ---- prep0: deg=0 (100K), W1 conv (2048 uint4), W2 conv (3072 halfs) ----
__global__ void k_prep0(const float* __restrict__ W1, const float* __restrict__ W2) {
    int i = blockIdx.x * blockDim.x + threadIdx.x;
    if (i < N_NODES) g_dege[i] = 0;
    if (i < F_IN * F_HID / 8) {
        const float4* src = (const float4*)W1 + i * 2;
        float4 a = src[0], b = src[1];
        __half2 h[4] = { __floats2half2_rn(a.x, a.y), __floats2half2_rn(a.z, a.w),
                         __floats2half2_rn(b.x, b.y), __floats2half2_rn(b.z, b.w) };
        ((uint4*)g_w1h)[i] = *(uint4*)h;
    }
    if (i < F_HID * 48) {
        int r = i / 48, c = i % 48;
        g_w2h[i] = __float2half_rn((c < F_OUT) ? W2[r * F_OUT + c] : 0.f);
    }
}

__global__ void k_count_deg(const int* __restrict__ ei) {
    int e = blockIdx.x * blockDim.x + threadIdx.x;
    if (e < N_EDGES) atomicAdd(&g_dege[__ldg(&ei[N_EDGES + e])], 1);
}

__global__ void k_dinv() {
    int n = blockIdx.x * blockDim.x + threadIdx.x;
    if (n < N_NODES) g_dinv[n] = rsqrtf((float)(g_dege[n] + 1));   // +1 self-loop
}

// ------- GEMM1 via tensor cores: h' = (dinv*x) @ W1, fp32 in-stage, fp16 out -------
#define XS_LD 72
__global__ __launch_bounds__(256) void k_gemm1_tc(const float* __restrict__ x) {
    __shared__ __align__(16) char sraw[46080];
    __half* ws = (__half*)sraw;                 // [64][72]  9216B
    __half* xs = (__half*)(sraw + 9216);        // [256][72] 36864B
    float*  fb = (float*)sraw;                  // aliased fp32 staging

    int tid  = threadIdx.x;
    int warp = tid >> 5;
    int lane = tid & 31;
    int nodebase = blockIdx.x * 256;

    wmma::fragment<wmma::accumulator, 16, 16, 16, float> c[2][4];
#pragma unroll
    for (int p = 0; p < 2; p++)
#pragma unroll
        for (int ct = 0; ct < 4; ct++) wmma::fill_fragment(c[p][ct], 0.f);

#pragma unroll 1
    for (int kb = 0; kb < 4; kb++) {
#pragma unroll
        for (int i = 0; i < 2; i++) {
            int u = tid + i * 256;
            int r = u >> 3, cc = u & 7;
            uint4 v = ((const uint4*)g_w1h)[(kb * 64 + r) * 8 + cc];
            *(uint4*)(ws + r * XS_LD + cc * 8) = v;
        }
        // stage x chunk from fp32, scale by dinv[node], convert to fp16
#pragma unroll
        for (int i = 0; i < 8; i++) {
            int u = tid + i * 256;
            int r = u >> 3, cc = u & 7;
            int node = nodebase + r;
            uint4 v = make_uint4(0u, 0u, 0u, 0u);
            if (node < N_NODES) {
                const float4* xp = (const float4*)(x + (size_t)node * F_IN + kb * 64 + cc * 8);
                float dv = g_dinv[node];
                float4 a = xp[0], b = xp[1];
                __half2 hh[4] = { __floats2half2_rn(dv * a.x, dv * a.y),
                                  __floats2half2_rn(dv * a.z, dv * a.w),
                                  __floats2half2_rn(dv * b.x, dv * b.y),
                                  __floats2half2_rn(dv * b.z, dv * b.w) };
                v = *(uint4*)hh;
            }
            *(uint4*)(xs + r * XS_LD + cc * 8) = v;
        }
        __syncthreads();

#pragma unroll
        for (int kt = 0; kt < 4; kt++) {
            wmma::fragment<wmma::matrix_a, 16, 16, 16, __half, wmma::row_major> a0, a1;
            wmma::load_matrix_sync(a0, xs + (warp * 32 +  0) * XS_LD + kt * 16, XS_LD);
            wmma::load_matrix_sync(a1, xs + (warp * 32 + 16) * XS_LD + kt * 16, XS_LD);
#pragma unroll
            for (int ct = 0; ct < 4; ct++) {
                wmma::fragment<wmma::matrix_b, 16, 16, 16, __half, wmma::row_major> b;
                wmma::load_matrix_sync(b, ws + kt * 16 * XS_LD + ct * 16, XS_LD);
                wmma::mma_sync(c[0][ct], a0, b, c[0][ct]);
                wmma::mma_sync(c[1][ct], a1, b, c[1][ct]);
            }
        }
        __syncthreads();
    }

    float* myfb = fb + warp * 16 * 64;
#pragma unroll
    for (int p = 0; p < 2; p++) {
#pragma unroll
        for (int ct = 0; ct < 4; ct++)
            wmma::store_matrix_sync(myfb + ct * 16, c[p][ct], 64, wmma::mem_row_major);
        __syncwarp();

        int row = lane >> 1;
        int ph  = lane & 1;
        int node = nodebase + warp * 32 + p * 16 + row;
        if (node < N_NODES) {
            const float* fr = myfb + row * 64 + ph * 32;
            __half2* o = &g_h[(size_t)node * 32 + ph * 16];
#pragma unroll
            for (int j = 0; j < 16; j++)
                o[j] = __floats2half2_rn(fr[2 * j], fr[2 * j + 1]);
        }
        __syncwarp();
    }
}

// ---------------- exclusive scan of g_dege -> g_rowptr ----------------
__global__ __launch_bounds__(SCAN_B) void k_scan1() {
    __shared__ int sm[SCAN_B];
    int t = threadIdx.x;
    int i = blockIdx.x * SCAN_B + t;
    int v = (i < N_NODES) ? g_dege[i] : 0;
    sm[t] = v;
    __syncthreads();
    for (int o = 1; o < SCAN_B; o <<= 1) {
        int x = (t >= o) ? sm[t - o] : 0;
        __syncthreads();
        sm[t] += x;
        __syncthreads();
    }
    if (i < N_NODES) g_rowptr[i] = sm[t] - v;
    if (t == SCAN_B - 1) g_bsum[blockIdx.x] = sm[t];
}

__global__ __launch_bounds__(256) void k_scan2() {
    __shared__ int sm[256];
    int t = threadIdx.x;
    int v = (t < N_SCANB) ? g_bsum[t] : 0;
    sm[t] = v;
    __syncthreads();
    for (int o = 1; o < 256; o <<= 1) {
        int x = (t >= o) ? sm[t - o] : 0;
        __syncthreads();
        sm[t] += x;
        __syncthreads();
    }
    g_bsum[t] = sm[t] - v;
}

__global__ void k_scan3() {
    int i = blockIdx.x * blockDim.x + threadIdx.x;
    if (i < N_NODES) {
        int r = g_rowptr[i] + g_bsum[i / SCAN_B];
        g_rowptr[i] = r;
        g_cursor[i] = r;
    }
}

// counting sort: only src id stored (dinv scaling is pre-applied to rows)
__global__ void k_sort(const int* __restrict__ ei) {
    int e = blockIdx.x * blockDim.x + threadIdx.x;
    if (e < N_EDGES) {
        int s = __ldg(&ei[e]);
        int d = __ldg(&ei[N_EDGES + e]);
        int pos = atomicAdd(&g_cursor[d], 1);
        g_srcs[pos] = s;
    }
}

// ------- layer-1 aggregation + dinv + bias + relu: warp/node, 4 edges/warp-load ---
__global__ __launch_bounds__(256) void k_agg1(const float* __restrict__ b1) {
    int node = (blockIdx.x * 256 + threadIdx.x) >> 5;
    int lane = threadIdx.x & 31;
    if (node >= N_NODES) return;
    int g  = lane >> 3;
    int li = lane & 7;

    float acc[8];
    {   // self contribution h'[node] (group 0 only)
        uint4 sv = *((const uint4*)(g_h + (size_t)node * 32) + li);
        __half2* hp = (__half2*)&sv;
        float m0 = (g == 0) ? 1.f : 0.f;
#pragma unroll
        for (int t = 0; t < 4; t++) {
            float2 f = __half22float2(hp[t]);
            acc[2 * t]     = m0 * f.x;
            acc[2 * t + 1] = m0 * f.y;
        }
    }

    int start = g_rowptr[node];
    int cnt   = g_dege[node];
    for (int base = 0; base < cnt; base += 32) {
        int idx = base + lane;
        int rec = (idx < cnt) ? g_srcs[start + idx] : -1;
        uint4 v[8];
#pragma unroll
        for (int j = 0; j < 8; j++) {           // 1 shfl + 1 predicated load per edge
            int src = __shfl_sync(0xFFFFFFFFu, rec, 4 * j + g);
            v[j] = make_uint4(0u, 0u, 0u, 0u);
            if (src >= 0)
                v[j] = *((const uint4*)(g_h + (size_t)src * 32) + li);
        }
#pragma unroll
        for (int j = 0; j < 8; j++) {
            __half2* hp = (__half2*)&v[j];
#pragma unroll
            for (int t = 0; t < 4; t++) {
                float2 f = __half22float2(hp[t]);
                acc[2 * t]     += f.x;
                acc[2 * t + 1] += f.y;
            }
        }
    }

#pragma unroll
    for (int k = 0; k < 8; k++) {
        acc[k] += __shfl_xor_sync(0xFFFFFFFFu, acc[k], 8);
        acc[k] += __shfl_xor_sync(0xFFFFFFFFu, acc[k], 16);
    }

    if (g == 0) {
        float dv = g_dinv[node];
        float4 ba = ((const float4*)b1)[li * 2];
        float4 bb = ((const float4*)b1)[li * 2 + 1];
        __half2 h[4];
        h[0] = __floats2half2_rn(fmaxf(dv * acc[0] + ba.x, 0.f), fmaxf(dv * acc[1] + ba.y, 0.f));
        h[1] = __floats2half2_rn(fmaxf(dv * acc[2] + ba.z, 0.f), fmaxf(dv * acc[3] + ba.w, 0.f));
        h[2] = __floats2half2_rn(fmaxf(dv * acc[4] + bb.x, 0.f), fmaxf(dv * acc[5] + bb.y, 0.f));
        h[3] = __floats2half2_rn(fmaxf(dv * acc[6] + bb.z, 0.f), fmaxf(dv * acc[7] + bb.w, 0.f));
        *((uint4*)(g_hr + (size_t)node * 64) + li) = *(uint4*)h;
    }
}

// ------- GEMM2 via tensor cores: h2' = dinv * (h_r @ W2), fp16 out ------
__global__ __launch_bounds__(256) void k_gemm2_tc() {
    __shared__ __align__(16) char sraw[46080];
    __half* ws = (__half*)sraw;                 // [64][72]  9216B
    __half* hs = (__half*)(sraw + 9216);        // [256][72] 36864B
    float*  fb = (float*)sraw;                  // aliased

    int tid  = threadIdx.x;
    int warp = tid >> 5;
    int lane = tid & 31;
    int nodebase = blockIdx.x * 256;

    for (int u = tid; u < 384; u += 256) {
        int r = u / 6, c = u % 6;
        uint4 v = ((const uint4*)g_w2h)[u];
        *(uint4*)(ws + r * XS_LD + c * 8) = v;
    }
#pragma unroll
    for (int i = 0; i < 8; i++) {
        int u = tid + i * 256;
        int r = u >> 3, c = u & 7;
        int node = nodebase + r;
        uint4 v = make_uint4(0u, 0u, 0u, 0u);
        if (node < N_NODES)
            v = *((const uint4*)(g_hr + (size_t)node * 64) + c);
        *(uint4*)(hs + r * XS_LD + c * 8) = v;
    }
    __syncthreads();

    wmma::fragment<wmma::accumulator, 16, 16, 16, float> c[2][3];
#pragma unroll
    for (int p = 0; p < 2; p++)
#pragma unroll
        for (int ct = 0; ct < 3; ct++) wmma::fill_fragment(c[p][ct], 0.f);

#pragma unroll
    for (int kt = 0; kt < 4; kt++) {
        wmma::fragment<wmma::matrix_a, 16, 16, 16, __half, wmma::row_major> a0, a1;
        wmma::load_matrix_sync(a0, hs + (warp * 32 +  0) * XS_LD + kt * 16, XS_LD);
        wmma::load_matrix_sync(a1, hs + (warp * 32 + 16) * XS_LD + kt * 16, XS_LD);
#pragma unroll
        for (int ct = 0; ct < 3; ct++) {
            wmma::fragment<wmma::matrix_b, 16, 16, 16, __half, wmma::row_major> b;
            wmma::load_matrix_sync(b, ws + kt * 16 * XS_LD + ct * 16, XS_LD);
            wmma::mma_sync(c[0][ct], a0, b, c[0][ct]);
            wmma::mma_sync(c[1][ct], a1, b, c[1][ct]);
        }
    }
    __syncthreads();

    float* myfb = fb + warp * 16 * 64;
#pragma unroll
    for (int p = 0; p < 2; p++) {
#pragma unroll
        for (int ct = 0; ct < 3; ct++)
            wmma::store_matrix_sync(myfb + ct * 16, c[p][ct], 64, wmma::mem_row_major);
        __syncwarp();

        int row = lane >> 1;
        int ph  = lane & 1;
        int node = nodebase + warp * 32 + p * 16 + row;
        if (node < N_NODES) {
            float dv = g_dinv[node];               // pre-scale for layer-2 gather
            const float* fr = myfb + row * 64 + ph * 20;
            __half2* o = &g_h2[(size_t)node * 20 + ph * 10];
#pragma unroll
            for (int j = 0; j < 10; j++)
                o[j] = __floats2half2_rn(dv * fr[2 * j], dv * fr[2 * j + 1]);
        }
        __syncwarp();
    }
}

// -- layer-2 aggregation + dinv + b2 + log-softmax: warp/node, 4 edges/warp-load --
__global__ __launch_bounds__(256) void k_agg2(float* __restrict__ out,
                                              const float* __restrict__ b2) {
    int node = (blockIdx.x * 256 + threadIdx.x) >> 5;
    int lane = threadIdx.x & 31;
    if (node >= N_NODES) return;
    int g  = lane >> 3;
    int li = lane & 7;
    bool fvalid = (li < 5);

    float acc[8];
    {
        uint4 sv = make_uint4(0u, 0u, 0u, 0u);
        if (fvalid) sv = *((const uint4*)(g_h2 + (size_t)node * 20) + li);
        __half2* hp = (__half2*)&sv;
        float m0 = (g == 0) ? 1.f : 0.f;
#pragma unroll
        for (int t = 0; t < 4; t++) {
            float2 f = __half22float2(hp[t]);
            acc[2 * t]     = m0 * f.x;
            acc[2 * t + 1] = m0 * f.y;
        }
    }

    int start = g_rowptr[node];
    int cnt   = g_dege[node];
    for (int base = 0; base < cnt; base += 32) {
        int idx = base + lane;
        int rec = (idx < cnt) ? g_srcs[start + idx] : -1;
        uint4 v[8];
#pragma unroll
        for (int j = 0; j < 8; j++) {
            int src = __shfl_sync(0xFFFFFFFFu, rec, 4 * j + g);
            v[j] = make_uint4(0u, 0u, 0u, 0u);
            if (fvalid && src >= 0)
                v[j] = *((const uint4*)(g_h2 + (size_t)src * 20) + li);
        }
#pragma unroll
        for (int j = 0; j < 8; j++) {
            __half2* hp = (__half2*)&v[j];
#pragma unroll
            for (int t = 0; t < 4; t++) {
                float2 f = __half22float2(hp[t]);
                acc[2 * t]     += f.x;
                acc[2 * t + 1] += f.y;
            }
        }
    }

#pragma unroll
    for (int k = 0; k < 8; k++) {
        acc[k] += __shfl_xor_sync(0xFFFFFFFFu, acc[k], 8);
        acc[k] += __shfl_xor_sync(0xFFFFFFFFu, acc[k], 16);
    }

    bool own = (g == 0) && fvalid;
    float vals[8];
    if (own) {
        float dv = g_dinv[node];
        float4 ba = ((const float4*)b2)[li * 2];
        float4 bb = ((const float4*)b2)[li * 2 + 1];
        vals[0] = dv * acc[0] + ba.x; vals[1] = dv * acc[1] + ba.y;
        vals[2] = dv * acc[2] + ba.z; vals[3] = dv * acc[3] + ba.w;
        vals[4] = dv * acc[4] + bb.x; vals[5] = dv * acc[5] + bb.y;
        vals[6] = dv * acc[6] + bb.z; vals[7] = dv * acc[7] + bb.w;
    } else {
#pragma unroll
        for (int k = 0; k < 8; k++) vals[k] = -3.4e38f;
    }

    float mx = vals[0];
#pragma unroll
    for (int k = 1; k < 8; k++) mx = fmaxf(mx, vals[k]);
#pragma unroll
    for (int o = 16; o > 0; o >>= 1)
        mx = fmaxf(mx, __shfl_xor_sync(0xFFFFFFFFu, mx, o));

    float s = 0.f;
    if (own) {
#pragma unroll
        for (int k = 0; k < 8; k++) s += expf(vals[k] - mx);
    }
#pragma unroll
    for (int o = 16; o > 0; o >>= 1)
        s += __shfl_xor_sync(0xFFFFFFFFu, s, o);

    float ls = logf(s) + mx;
    if (own) {
        float4* o0 = (float4*)(out + (size_t)node * 40 + li * 8);
        o0[0] = make_float4(vals[0] - ls, vals[1] - ls, vals[2] - ls, vals[3] - ls);
        o0[1] = make_float4(vals[4] - ls, vals[5] - ls, vals[6] - ls, vals[7] - ls);
    }
}

// ---------------- launch ----------------
extern "C" void kernel_launch(void* const* d_in, const int* in_sizes, int n_in,
                              void* d_out, int out_size) {
    const float* x  = (const float*)d_in[0];
    const int*   ei = (const int*)d_in[1];   // int32 (JAX x64 disabled)
    const float* W1 = (const float*)d_in[2];
    const float* b1 = (const float*)d_in[3];
    const float* W2 = (const float*)d_in[4];
    const float* b2 = (const float*)d_in[5];
    float*       out = (float*)d_out;

    const int TB = 256;
    k_prep0    <<<(N_NODES + TB - 1) / TB, TB>>>(W1, W2);
    k_count_deg<<<(N_EDGES + TB - 1) / TB, TB>>>(ei);
    k_dinv     <<<(N_NODES + TB - 1) / TB, TB>>>();
    // 4th launch = ncu capture slot: gemm1_tc (now with in-kernel fp32->fp16)
    k_gemm1_tc <<<(N_NODES + 255) / 256, 256>>>(x);
    k_scan1    <<<N_SCANB, SCAN_B>>>();
    k_scan2    <<<1, 256>>>();
    k_scan3    <<<(N_NODES + TB - 1) / TB, TB>>>();
    k_sort     <<<(N_EDGES + TB - 1) / TB, TB>>>(ei);

    k_agg1     <<<(N_NODES * 32 + TB - 1) / TB, TB>>>(b1);
    k_gemm2_tc <<<(N_NODES + 255) / 256, 256>>>();
    k_agg2     <<<(N_NODES * 32 + TB - 1) / TB, TB>>>(out, b2);
}

// round 15
// speedup vs baseline: 1.5316x; 1.0980x over previous
#include <cuda_runtime.h>
#include <cuda_fp16.h>
#include <mma.h>
using namespace nvcuda;

#define N_NODES 100000
#define N_EDGES 3200000
#define F_IN    256
#define F_HID   64
#define F_OUT   40
#define SCAN_B  512
#define N_SCANB ((N_NODES + SCAN_B - 1) / SCAN_B)   // 196

// ---------------- scratch (device globals: alloc-free) ----------------
__device__ int     g_dege  [N_NODES];
__device__ float   g_dinv  [N_NODES];
__device__ int     g_rowptr[N_NODES];
__device__ int     g_cursor[N_NODES];
__device__ int     g_bsum  [256];
__device__ int     g_srcs  [N_EDGES];      // dst-sorted src ids (4B/edge)
__device__ __half  g_xh  [(size_t)N_NODES * F_IN];  // dinv*x in fp16
__device__ __half  g_w1h [F_IN * F_HID];            // W1 fp16
__device__ __half  g_w2h [F_HID * 48];              // W2 fp16, N padded 40->48
__device__ __half2 g_h   [N_NODES * 32];   // h' = (dinv*x)@W1, fp16, 128B rows
__device__ __half  g_hr  [(size_t)N_NODES * 64];    // relu(dinv*agg+b1), fp16
__device__ __half2 g_h2  [N_NODES * 20];   // h2' = dinv*(hr@W2), fp16, 80B rows

// ---- prep0: deg=0 (100K), W1 conv (2048 uint4), W2 conv (3072 halfs) ----
__global__ void k_prep0(const float* __restrict__ W1, const float* __restrict__ W2) {
    int i = blockIdx.x * blockDim.x + threadIdx.x;
    if (i < N_NODES) g_dege[i] = 0;
    if (i < F_IN * F_HID / 8) {
        const float4* src = (const float4*)W1 + i * 2;
        float4 a = src[0], b = src[1];
        __half2 h[4] = { __floats2half2_rn(a.x, a.y), __floats2half2_rn(a.z, a.w),
                         __floats2half2_rn(b.x, b.y), __floats2half2_rn(b.z, b.w) };
        ((uint4*)g_w1h)[i] = *(uint4*)h;
    }
    if (i < F_HID * 48) {
        int r = i / 48, c = i % 48;
        g_w2h[i] = __float2half_rn((c < F_OUT) ? W2[r * F_OUT + c] : 0.f);
    }
}

__global__ void k_count_deg(const int* __restrict__ ei) {
    int e = blockIdx.x * blockDim.x + threadIdx.x;
    if (e < N_EDGES) atomicAdd(&g_dege[__ldg(&ei[N_EDGES + e])], 1);
}

// streaming convert with dinv fused: g_xh = fp16(dinv[node] * x).
// dinv computed inline from g_dege (k_dinv runs later; no dependency).
__global__ void k_convx_scaled(const float* __restrict__ x) {
    size_t i = (size_t)blockIdx.x * blockDim.x + threadIdx.x;   // one uint4 = 8 halfs
    if (i >= (size_t)N_NODES * F_IN / 8) return;
    int node = (int)(i >> 5);                                   // 32 uint4 per row
    float dv = rsqrtf((float)(g_dege[node] + 1));
    const float4* src = (const float4*)x + i * 2;
    float4 a = src[0], b = src[1];
    __half2 h[4] = { __floats2half2_rn(dv * a.x, dv * a.y),
                     __floats2half2_rn(dv * a.z, dv * a.w),
                     __floats2half2_rn(dv * b.x, dv * b.y),
                     __floats2half2_rn(dv * b.z, dv * b.w) };
    ((uint4*)g_xh)[i] = *(uint4*)h;
}

__global__ void k_dinv() {
    int n = blockIdx.x * blockDim.x + threadIdx.x;
    if (n < N_NODES) g_dinv[n] = rsqrtf((float)(g_dege[n] + 1));   // +1 self-loop
}

// ------- GEMM1 via tensor cores: h' = (dinv*x) @ W1, fp16 staged, fp16 out -------
#define XS_LD 72
__global__ __launch_bounds__(256) void k_gemm1_tc() {
    __shared__ __align__(16) char sraw[46080];
    __half* ws = (__half*)sraw;                 // [64][72]  9216B
    __half* xs = (__half*)(sraw + 9216);        // [256][72] 36864B
    float*  fb = (float*)sraw;                  // aliased fp32 staging

    int tid  = threadIdx.x;
    int warp = tid >> 5;
    int lane = tid & 31;
    int nodebase = blockIdx.x * 256;

    wmma::fragment<wmma::accumulator, 16, 16, 16, float> c[2][4];
#pragma unroll
    for (int p = 0; p < 2; p++)
#pragma unroll
        for (int ct = 0; ct < 4; ct++) wmma::fill_fragment(c[p][ct], 0.f);

#pragma unroll 1
    for (int kb = 0; kb < 4; kb++) {
#pragma unroll
        for (int i = 0; i < 2; i++) {
            int u = tid + i * 256;
            int r = u >> 3, cc = u & 7;
            uint4 v = ((const uint4*)g_w1h)[(kb * 64 + r) * 8 + cc];
            *(uint4*)(ws + r * XS_LD + cc * 8) = v;
        }
#pragma unroll
        for (int i = 0; i < 8; i++) {
            int u = tid + i * 256;
            int r = u >> 3, cc = u & 7;
            int node = nodebase + r;
            uint4 v = make_uint4(0u, 0u, 0u, 0u);
            if (node < N_NODES)
                v = *(const uint4*)(g_xh + (size_t)node * F_IN + kb * 64 + cc * 8);
            *(uint4*)(xs + r * XS_LD + cc * 8) = v;
        }
        __syncthreads();

#pragma unroll
        for (int kt = 0; kt < 4; kt++) {
            wmma::fragment<wmma::matrix_a, 16, 16, 16, __half, wmma::row_major> a0, a1;
            wmma::load_matrix_sync(a0, xs + (warp * 32 +  0) * XS_LD + kt * 16, XS_LD);
            wmma::load_matrix_sync(a1, xs + (warp * 32 + 16) * XS_LD + kt * 16, XS_LD);
#pragma unroll
            for (int ct = 0; ct < 4; ct++) {
                wmma::fragment<wmma::matrix_b, 16, 16, 16, __half, wmma::row_major> b;
                wmma::load_matrix_sync(b, ws + kt * 16 * XS_LD + ct * 16, XS_LD);
                wmma::mma_sync(c[0][ct], a0, b, c[0][ct]);
                wmma::mma_sync(c[1][ct], a1, b, c[1][ct]);
            }
        }
        __syncthreads();
    }

    float* myfb = fb + warp * 16 * 64;
#pragma unroll
    for (int p = 0; p < 2; p++) {
#pragma unroll
        for (int ct = 0; ct < 4; ct++)
            wmma::store_matrix_sync(myfb + ct * 16, c[p][ct], 64, wmma::mem_row_major);
        __syncwarp();

        int row = lane >> 1;
        int ph  = lane & 1;
        int node = nodebase + warp * 32 + p * 16 + row;
        if (node < N_NODES) {
            const float* fr = myfb + row * 64 + ph * 32;
            __half2* o = &g_h[(size_t)node * 32 + ph * 16];
#pragma unroll
            for (int j = 0; j < 16; j++)
                o[j] = __floats2half2_rn(fr[2 * j], fr[2 * j + 1]);
        }
        __syncwarp();
    }
}

// ---------------- exclusive scan of g_dege -> g_rowptr ----------------
__global__ __launch_bounds__(SCAN_B) void k_scan1() {
    __shared__ int sm[SCAN_B];
    int t = threadIdx.x;
    int i = blockIdx.x * SCAN_B + t;
    int v = (i < N_NODES) ? g_dege[i] : 0;
    sm[t] = v;
    __syncthreads();
    for (int o = 1; o < SCAN_B; o <<= 1) {
        int x = (t >= o) ? sm[t - o] : 0;
        __syncthreads();
        sm[t] += x;
        __syncthreads();
    }
    if (i < N_NODES) g_rowptr[i] = sm[t] - v;
    if (t == SCAN_B - 1) g_bsum[blockIdx.x] = sm[t];
}

__global__ __launch_bounds__(256) void k_scan2() {
    __shared__ int sm[256];
    int t = threadIdx.x;
    int v = (t < N_SCANB) ? g_bsum[t] : 0;
    sm[t] = v;
    __syncthreads();
    for (int o = 1; o < 256; o <<= 1) {
        int x = (t >= o) ? sm[t - o] : 0;
        __syncthreads();
        sm[t] += x;
        __syncthreads();
    }
    g_bsum[t] = sm[t] - v;
}

__global__ void k_scan3() {
    int i = blockIdx.x * blockDim.x + threadIdx.x;
    if (i < N_NODES) {
        int r = g_rowptr[i] + g_bsum[i / SCAN_B];
        g_rowptr[i] = r;
        g_cursor[i] = r;
    }
}

// counting sort: only src id stored
__global__ void k_sort(const int* __restrict__ ei) {
    int e = blockIdx.x * blockDim.x + threadIdx.x;
    if (e < N_EDGES) {
        int s = __ldg(&ei[e]);
        int d = __ldg(&ei[N_EDGES + e]);
        int pos = atomicAdd(&g_cursor[d], 1);
        g_srcs[pos] = s;
    }
}

// ------- layer-1 aggregation + dinv + bias + relu: warp/node, 4 edges/warp-load ---
__global__ __launch_bounds__(256) void k_agg1(const float* __restrict__ b1) {
    int node = (blockIdx.x * 256 + threadIdx.x) >> 5;
    int lane = threadIdx.x & 31;
    if (node >= N_NODES) return;
    int g  = lane >> 3;
    int li = lane & 7;

    float acc[8];
    {   // self contribution h'[node] (group 0 only)
        uint4 sv = *((const uint4*)(g_h + (size_t)node * 32) + li);
        __half2* hp = (__half2*)&sv;
        float m0 = (g == 0) ? 1.f : 0.f;
#pragma unroll
        for (int t = 0; t < 4; t++) {
            float2 f = __half22float2(hp[t]);
            acc[2 * t]     = m0 * f.x;
            acc[2 * t + 1] = m0 * f.y;
        }
    }

    int start = g_rowptr[node];
    int cnt   = g_dege[node];
    for (int base = 0; base < cnt; base += 32) {
        int idx = base + lane;
        int rec = (idx < cnt) ? g_srcs[start + idx] : -1;
        uint4 v[8];
#pragma unroll
        for (int j = 0; j < 8; j++) {           // 1 shfl + 1 predicated load per edge
            int src = __shfl_sync(0xFFFFFFFFu, rec, 4 * j + g);
            v[j] = make_uint4(0u, 0u, 0u, 0u);
            if (src >= 0)
                v[j] = *((const uint4*)(g_h + (size_t)src * 32) + li);
        }
#pragma unroll
        for (int j = 0; j < 8; j++) {
            __half2* hp = (__half2*)&v[j];
#pragma unroll
            for (int t = 0; t < 4; t++) {
                float2 f = __half22float2(hp[t]);
                acc[2 * t]     += f.x;
                acc[2 * t + 1] += f.y;
            }
        }
    }

#pragma unroll
    for (int k = 0; k < 8; k++) {
        acc[k] += __shfl_xor_sync(0xFFFFFFFFu, acc[k], 8);
        acc[k] += __shfl_xor_sync(0xFFFFFFFFu, acc[k], 16);
    }

    if (g == 0) {
        float dv = g_dinv[node];
        float4 ba = ((const float4*)b1)[li * 2];
        float4 bb = ((const float4*)b1)[li * 2 + 1];
        __half2 h[4];
        h[0] = __floats2half2_rn(fmaxf(dv * acc[0] + ba.x, 0.f), fmaxf(dv * acc[1] + ba.y, 0.f));
        h[1] = __floats2half2_rn(fmaxf(dv * acc[2] + ba.z, 0.f), fmaxf(dv * acc[3] + ba.w, 0.f));
        h[2] = __floats2half2_rn(fmaxf(dv * acc[4] + bb.x, 0.f), fmaxf(dv * acc[5] + bb.y, 0.f));
        h[3] = __floats2half2_rn(fmaxf(dv * acc[6] + bb.z, 0.f), fmaxf(dv * acc[7] + bb.w, 0.f));
        *((uint4*)(g_hr + (size_t)node * 64) + li) = *(uint4*)h;
    }
}

// ------- GEMM2 via tensor cores: h2' = dinv * (h_r @ W2), fp16 out ------
__global__ __launch_bounds__(256) void k_gemm2_tc() {
    __shared__ __align__(16) char sraw[46080];
    __half* ws = (__half*)sraw;                 // [64][72]  9216B
    __half* hs = (__half*)(sraw + 9216);        // [256][72] 36864B
    float*  fb = (float*)sraw;                  // aliased

    int tid  = threadIdx.x;
    int warp = tid >> 5;
    int lane = tid & 31;
    int nodebase = blockIdx.x * 256;

    for (int u = tid; u < 384; u += 256) {
        int r = u / 6, c = u % 6;
        uint4 v = ((const uint4*)g_w2h)[u];
        *(uint4*)(ws + r * XS_LD + c * 8) = v;
    }
#pragma unroll
    for (int i = 0; i < 8; i++) {
        int u = tid + i * 256;
        int r = u >> 3, c = u & 7;
        int node = nodebase + r;
        uint4 v = make_uint4(0u, 0u, 0u, 0u);
        if (node < N_NODES)
            v = *((const uint4*)(g_hr + (size_t)node * 64) + c);
        *(uint4*)(hs + r * XS_LD + c * 8) = v;
    }
    __syncthreads();

    wmma::fragment<wmma::accumulator, 16, 16, 16, float> c[2][3];
#pragma unroll
    for (int p = 0; p < 2; p++)
#pragma unroll
        for (int ct = 0; ct < 3; ct++) wmma::fill_fragment(c[p][ct], 0.f);

#pragma unroll
    for (int kt = 0; kt < 4; kt++) {
        wmma::fragment<wmma::matrix_a, 16, 16, 16, __half, wmma::row_major> a0, a1;
        wmma::load_matrix_sync(a0, hs + (warp * 32 +  0) * XS_LD + kt * 16, XS_LD);
        wmma::load_matrix_sync(a1, hs + (warp * 32 + 16) * XS_LD + kt * 16, XS_LD);
#pragma unroll
        for (int ct = 0; ct < 3; ct++) {
            wmma::fragment<wmma::matrix_b, 16, 16, 16, __half, wmma::row_major> b;
            wmma::load_matrix_sync(b, ws + kt * 16 * XS_LD + ct * 16, XS_LD);
            wmma::mma_sync(c[0][ct], a0, b, c[0][ct]);
            wmma::mma_sync(c[1][ct], a1, b, c[1][ct]);
        }
    }
    __syncthreads();

    float* myfb = fb + warp * 16 * 64;
#pragma unroll
    for (int p = 0; p < 2; p++) {
#pragma unroll
        for (int ct = 0; ct < 3; ct++)
            wmma::store_matrix_sync(myfb + ct * 16, c[p][ct], 64, wmma::mem_row_major);
        __syncwarp();

        int row = lane >> 1;
        int ph  = lane & 1;
        int node = nodebase + warp * 32 + p * 16 + row;
        if (node < N_NODES) {
            float dv = g_dinv[node];               // pre-scale for layer-2 gather
            const float* fr = myfb + row * 64 + ph * 20;
            __half2* o = &g_h2[(size_t)node * 20 + ph * 10];
#pragma unroll
            for (int j = 0; j < 10; j++)
                o[j] = __floats2half2_rn(dv * fr[2 * j], dv * fr[2 * j + 1]);
        }
        __syncwarp();
    }
}

// -- layer-2 aggregation + dinv + b2 + log-softmax: warp/node, 4 edges/warp-load --
__global__ __launch_bounds__(256) void k_agg2(float* __restrict__ out,
                                              const float* __restrict__ b2) {
    int node = (blockIdx.x * 256 + threadIdx.x) >> 5;
    int lane = threadIdx.x & 31;
    if (node >= N_NODES) return;
    int g  = lane >> 3;
    int li = lane & 7;
    bool fvalid = (li < 5);

    float acc[8];
    {
        uint4 sv = make_uint4(0u, 0u, 0u, 0u);
        if (fvalid) sv = *((const uint4*)(g_h2 + (size_t)node * 20) + li);
        __half2* hp = (__half2*)&sv;
        float m0 = (g == 0) ? 1.f : 0.f;
#pragma unroll
        for (int t = 0; t < 4; t++) {
            float2 f = __half22float2(hp[t]);
            acc[2 * t]     = m0 * f.x;
            acc[2 * t + 1] = m0 * f.y;
        }
    }

    int start = g_rowptr[node];
    int cnt   = g_dege[node];
    for (int base = 0; base < cnt; base += 32) {
        int idx = base + lane;
        int rec = (idx < cnt) ? g_srcs[start + idx] : -1;
        uint4 v[8];
#pragma unroll
        for (int j = 0; j < 8; j++) {
            int src = __shfl_sync(0xFFFFFFFFu, rec, 4 * j + g);
            v[j] = make_uint4(0u, 0u, 0u, 0u);
            if (fvalid && src >= 0)
                v[j] = *((const uint4*)(g_h2 + (size_t)src * 20) + li);
        }
#pragma unroll
        for (int j = 0; j < 8; j++) {
            __half2* hp = (__half2*)&v[j];
#pragma unroll
            for (int t = 0; t < 4; t++) {
                float2 f = __half22float2(hp[t]);
                acc[2 * t]     += f.x;
                acc[2 * t + 1] += f.y;
            }
        }
    }

#pragma unroll
    for (int k = 0; k < 8; k++) {
        acc[k] += __shfl_xor_sync(0xFFFFFFFFu, acc[k], 8);
        acc[k] += __shfl_xor_sync(0xFFFFFFFFu, acc[k], 16);
    }

    bool own = (g == 0) && fvalid;
    float vals[8];
    if (own) {
        float dv = g_dinv[node];
        float4 ba = ((const float4*)b2)[li * 2];
        float4 bb = ((const float4*)b2)[li * 2 + 1];
        vals[0] = dv * acc[0] + ba.x; vals[1] = dv * acc[1] + ba.y;
        vals[2] = dv * acc[2] + ba.z; vals[3] = dv * acc[3] + ba.w;
        vals[4] = dv * acc[4] + bb.x; vals[5] = dv * acc[5] + bb.y;
        vals[6] = dv * acc[6] + bb.z; vals[7] = dv * acc[7] + bb.w;
    } else {
#pragma unroll
        for (int k = 0; k < 8; k++) vals[k] = -3.4e38f;
    }

    float mx = vals[0];
#pragma unroll
    for (int k = 1; k < 8; k++) mx = fmaxf(mx, vals[k]);
#pragma unroll
    for (int o = 16; o > 0; o >>= 1)
        mx = fmaxf(mx, __shfl_xor_sync(0xFFFFFFFFu, mx, o));

    float s = 0.f;
    if (own) {
#pragma unroll
        for (int k = 0; k < 8; k++) s += expf(vals[k] - mx);
    }
#pragma unroll
    for (int o = 16; o > 0; o >>= 1)
        s += __shfl_xor_sync(0xFFFFFFFFu, s, o);

    float ls = logf(s) + mx;
    if (own) {
        float4* o0 = (float4*)(out + (size_t)node * 40 + li * 8);
        o0[0] = make_float4(vals[0] - ls, vals[1] - ls, vals[2] - ls, vals[3] - ls);
        o0[1] = make_float4(vals[4] - ls, vals[5] - ls, vals[6] - ls, vals[7] - ls);
    }
}

// ---------------- launch ----------------
extern "C" void kernel_launch(void* const* d_in, const int* in_sizes, int n_in,
                              void* d_out, int out_size) {
    const float* x  = (const float*)d_in[0];
    const int*   ei = (const int*)d_in[1];   // int32 (JAX x64 disabled)
    const float* W1 = (const float*)d_in[2];
    const float* b1 = (const float*)d_in[3];
    const float* W2 = (const float*)d_in[4];
    const float* b2 = (const float*)d_in[5];
    float*       out = (float*)d_out;

    const int TB = 256;
    k_prep0       <<<(N_NODES + TB - 1) / TB, TB>>>(W1, W2);
    k_count_deg   <<<(N_EDGES + TB - 1) / TB, TB>>>(ei);
    k_convx_scaled<<<(int)(((size_t)N_NODES * F_IN / 8 + TB - 1) / TB), TB>>>(x);
    // 4th launch = ncu capture slot: gemm1_tc (fp16-staged again)
    k_gemm1_tc    <<<(N_NODES + 255) / 256, 256>>>();
    k_dinv        <<<(N_NODES + TB - 1) / TB, TB>>>();
    k_scan1       <<<N_SCANB, SCAN_B>>>();
    k_scan2       <<<1, 256>>>();
    k_scan3       <<<(N_NODES + TB - 1) / TB, TB>>>();
    k_sort        <<<(N_EDGES + TB - 1) / TB, TB>>>(ei);

    k_agg1        <<<(N_NODES * 32 + TB - 1) / TB, TB>>>(b1);
    k_gemm2_tc    <<<(N_NODES + 255) / 256, 256>>>();
    k_agg2        <<<(N_NODES * 32 + TB - 1) / TB, TB>>>(out, b2);
}

// round 17
// speedup vs baseline: 1.5423x; 1.0069x over previous
#include <cuda_runtime.h>
#include <cuda_fp16.h>
#include <mma.h>
#include <cstdint>
using namespace nvcuda;

#define N_NODES 100000
#define N_EDGES 3200000
#define F_IN    256
#define F_HID   64
#define F_OUT   40
#define SCAN_B  512
#define N_SCANB ((N_NODES + SCAN_B - 1) / SCAN_B)   // 196

// ---------------- scratch (device globals: alloc-free) ----------------
__device__ int     g_dege  [N_NODES];
__device__ float   g_dinv  [N_NODES];
__device__ int     g_rowptr[N_NODES];
__device__ int     g_cursor[N_NODES];
__device__ int     g_bsum  [256];
__device__ int     g_srcs  [N_EDGES];      // dst-sorted src ids (4B/edge)
__device__ __half  g_xh  [(size_t)N_NODES * F_IN];  // dinv*x in fp16
__device__ __half  g_w1h [F_IN * F_HID];            // W1 fp16
__device__ __half  g_w2h [F_HID * 48];              // W2 fp16, N padded 40->48
__device__ __half2 g_h   [N_NODES * 32];   // h' = (dinv*x)@W1, fp16, 128B rows
__device__ __half  g_hr  [(size_t)N_NODES * 64];    // relu(dinv*agg+b1), fp16
__device__ __half2 g_h2  [(size_t)N_NODES * 32];    // h2' rows padded to 128B (40 used)

// ---------------- cp.async helpers ----------------
__device__ __forceinline__ void cp16(unsigned dst, const void* src, bool valid) {
    asm volatile("cp.async.cg.shared.global [%0], [%1], 16, %2;"
                 :: "r"(dst), "l"(src), "r"(valid ? 16 : 0));
}
__device__ __forceinline__ void cp_commit() {
    asm volatile("cp.async.commit_group;");
}
template <int N>
__device__ __forceinline__ void cp_wait() {
    asm volatile("cp.async.wait_group %0;" :: "n"(N));
}

// ---- prep0: deg=0 (100K), W1 conv (2048 uint4), W2 conv (3072 halfs) ----
__global__ void k_prep0(const float* __restrict__ W1, const float* __restrict__ W2) {
    int i = blockIdx.x * blockDim.x + threadIdx.x;
    if (i < N_NODES) g_dege[i] = 0;
    if (i < F_IN * F_HID / 8) {
        const float4* src = (const float4*)W1 + i * 2;
        float4 a = src[0], b = src[1];
        __half2 h[4] = { __floats2half2_rn(a.x, a.y), __floats2half2_rn(a.z, a.w),
                         __floats2half2_rn(b.x, b.y), __floats2half2_rn(b.z, b.w) };
        ((uint4*)g_w1h)[i] = *(uint4*)h;
    }
    if (i < F_HID * 48) {
        int r = i / 48, c = i % 48;
        g_w2h[i] = __float2half_rn((c < F_OUT) ? W2[r * F_OUT + c] : 0.f);
    }
}

__global__ void k_count_deg(const int* __restrict__ ei) {
    int e = blockIdx.x * blockDim.x + threadIdx.x;
    if (e < N_EDGES) atomicAdd(&g_dege[__ldg(&ei[N_EDGES + e])], 1);
}

// streaming convert with dinv fused: g_xh = fp16(dinv[node] * x)
__global__ void k_convx_scaled(const float* __restrict__ x) {
    size_t i = (size_t)blockIdx.x * blockDim.x + threadIdx.x;   // one uint4 = 8 halfs
    if (i >= (size_t)N_NODES * F_IN / 8) return;
    int node = (int)(i >> 5);                                   // 32 uint4 per row
    float dv = rsqrtf((float)(g_dege[node] + 1));
    const float4* src = (const float4*)x + i * 2;
    float4 a = src[0], b = src[1];
    __half2 h[4] = { __floats2half2_rn(dv * a.x, dv * a.y),
                     __floats2half2_rn(dv * a.z, dv * a.w),
                     __floats2half2_rn(dv * b.x, dv * b.y),
                     __floats2half2_rn(dv * b.z, dv * b.w) };
    ((uint4*)g_xh)[i] = *(uint4*)h;
}

// ------- GEMM1 tensor cores, cp.async double-buffered x tiles, full-W1 staged ----
// dyn smem: ws [256][72] (full W1, 36864B) | xs0 [256][72] | xs1 [256][72]
// fb (fp32 writeback staging) aliases the front 32KB after compute is done.
#define XS_LD 72
#define SM_WS  0
#define SM_XS0 36864
#define SM_XS1 73728
#define SM_TOT 110592
extern __shared__ __align__(16) char dynsm[];

__device__ __forceinline__ void stage_x_chunk(__half* xs, int nodebase, int kb, int tid) {
#pragma unroll
    for (int i = 0; i < 8; i++) {
        int u = tid + i * 256;
        int r = u >> 3, c = u & 7;
        int node = nodebase + r;
        bool ok = node < N_NODES;
        const void* src = ok ? (const void*)(g_xh + (size_t)node * F_IN + kb * 64 + c * 8)
                             : (const void*)g_xh;
        unsigned dst = (unsigned)__cvta_generic_to_shared(xs + r * XS_LD + c * 8);
        cp16(dst, src, ok);
    }
}

__global__ __launch_bounds__(256) void k_gemm1_tc() {
    __half* ws  = (__half*)(dynsm + SM_WS);
    __half* xs0 = (__half*)(dynsm + SM_XS0);
    __half* xs1 = (__half*)(dynsm + SM_XS1);
    float*  fb  = (float*)dynsm;

    int tid  = threadIdx.x;
    int warp = tid >> 5;
    int lane = tid & 31;
    int nodebase = blockIdx.x * 256;

    // prologue: stage full W1 + x chunk 0, one cp.async group
#pragma unroll
    for (int i = 0; i < 8; i++) {
        int u = tid + i * 256;
        int r = u >> 3, c = u & 7;
        unsigned dst = (unsigned)__cvta_generic_to_shared(ws + r * XS_LD + c * 8);
        cp16(dst, (const uint4*)g_w1h + u, true);
    }
    stage_x_chunk(xs0, nodebase, 0, tid);
    cp_commit();

    wmma::fragment<wmma::accumulator, 16, 16, 16, float> c[2][4];
#pragma unroll
    for (int p = 0; p < 2; p++)
#pragma unroll
        for (int ct = 0; ct < 4; ct++) wmma::fill_fragment(c[p][ct], 0.f);

#pragma unroll
    for (int kb = 0; kb < 4; kb++) {
        if (kb < 3) {                    // prefetch next chunk into other buffer
            stage_x_chunk(((kb + 1) & 1) ? xs1 : xs0, nodebase, kb + 1, tid);
            cp_commit();
            cp_wait<1>();                // oldest group (chunk kb [+W1]) complete
        } else {
            cp_wait<0>();
        }
        __syncthreads();

        __half* xcur = (kb & 1) ? xs1 : xs0;
#pragma unroll
        for (int kt = 0; kt < 4; kt++) {
            wmma::fragment<wmma::matrix_a, 16, 16, 16, __half, wmma::row_major> a0, a1;
            wmma::load_matrix_sync(a0, xcur + (warp * 32 +  0) * XS_LD + kt * 16, XS_LD);
            wmma::load_matrix_sync(a1, xcur + (warp * 32 + 16) * XS_LD + kt * 16, XS_LD);
#pragma unroll
            for (int ct = 0; ct < 4; ct++) {
                wmma::fragment<wmma::matrix_b, 16, 16, 16, __half, wmma::row_major> b;
                wmma::load_matrix_sync(b, ws + (kb * 64 + kt * 16) * XS_LD + ct * 16, XS_LD);
                wmma::mma_sync(c[0][ct], a0, b, c[0][ct]);
                wmma::mma_sync(c[1][ct], a1, b, c[1][ct]);
            }
        }
        __syncthreads();   // mma reads done before buffer reuse / fb alias
    }

    float* myfb = fb + warp * 16 * 64;
#pragma unroll
    for (int p = 0; p < 2; p++) {
#pragma unroll
        for (int ct = 0; ct < 4; ct++)
            wmma::store_matrix_sync(myfb + ct * 16, c[p][ct], 64, wmma::mem_row_major);
        __syncwarp();

        int row = lane >> 1;
        int ph  = lane & 1;
        int node = nodebase + warp * 32 + p * 16 + row;
        if (node < N_NODES) {
            const float* fr = myfb + row * 64 + ph * 32;
            __half2* o = &g_h[(size_t)node * 32 + ph * 16];
#pragma unroll
            for (int j = 0; j < 16; j++)
                o[j] = __floats2half2_rn(fr[2 * j], fr[2 * j + 1]);
        }
        __syncwarp();
    }
}

// ---------------- exclusive scan of g_dege -> g_rowptr ----------------
__global__ __launch_bounds__(SCAN_B) void k_scan1() {
    __shared__ int sm[SCAN_B];
    int t = threadIdx.x;
    int i = blockIdx.x * SCAN_B + t;
    int v = (i < N_NODES) ? g_dege[i] : 0;
    sm[t] = v;
    __syncthreads();
    for (int o = 1; o < SCAN_B; o <<= 1) {
        int x = (t >= o) ? sm[t - o] : 0;
        __syncthreads();
        sm[t] += x;
        __syncthreads();
    }
    if (i < N_NODES) g_rowptr[i] = sm[t] - v;
    if (t == SCAN_B - 1) g_bsum[blockIdx.x] = sm[t];
}

__global__ __launch_bounds__(256) void k_scan2() {
    __shared__ int sm[256];
    int t = threadIdx.x;
    int v = (t < N_SCANB) ? g_bsum[t] : 0;
    sm[t] = v;
    __syncthreads();
    for (int o = 1; o < 256; o <<= 1) {
        int x = (t >= o) ? sm[t - o] : 0;
        __syncthreads();
        sm[t] += x;
        __syncthreads();
    }
    g_bsum[t] = sm[t] - v;
}

// scan3 + dinv folded
__global__ void k_scan3() {
    int i = blockIdx.x * blockDim.x + threadIdx.x;
    if (i < N_NODES) {
        int r = g_rowptr[i] + g_bsum[i / SCAN_B];
        g_rowptr[i] = r;
        g_cursor[i] = r;
        g_dinv[i]   = rsqrtf((float)(g_dege[i] + 1));   // +1 self-loop
    }
}

// counting sort: only src id stored
__global__ void k_sort(const int* __restrict__ ei) {
    int e = blockIdx.x * blockDim.x + threadIdx.x;
    if (e < N_EDGES) {
        int s = __ldg(&ei[e]);
        int d = __ldg(&ei[N_EDGES + e]);
        int pos = atomicAdd(&g_cursor[d], 1);
        g_srcs[pos] = s;
    }
}

// ------- layer-1 aggregation + dinv + bias + relu: warp/node, 4 edges/warp-load ---
__global__ __launch_bounds__(256) void k_agg1(const float* __restrict__ b1) {
    int node = (blockIdx.x * 256 + threadIdx.x) >> 5;
    int lane = threadIdx.x & 31;
    if (node >= N_NODES) return;
    int g  = lane >> 3;
    int li = lane & 7;

    float acc[8];
    {   // self contribution h'[node] (group 0 only)
        uint4 sv = *((const uint4*)(g_h + (size_t)node * 32) + li);
        __half2* hp = (__half2*)&sv;
        float m0 = (g == 0) ? 1.f : 0.f;
#pragma unroll
        for (int t = 0; t < 4; t++) {
            float2 f = __half22float2(hp[t]);
            acc[2 * t]     = m0 * f.x;
            acc[2 * t + 1] = m0 * f.y;
        }
    }

    int start = g_rowptr[node];
    int cnt   = g_dege[node];
    for (int base = 0; base < cnt; base += 32) {
        int idx = base + lane;
        int rec = (idx < cnt) ? g_srcs[start + idx] : -1;
        uint4 v[8];
#pragma unroll
        for (int j = 0; j < 8; j++) {           // 1 shfl + 1 predicated load per edge
            int src = __shfl_sync(0xFFFFFFFFu, rec, 4 * j + g);
            v[j] = make_uint4(0u, 0u, 0u, 0u);
            if (src >= 0)
                v[j] = *((const uint4*)(g_h + (size_t)src * 32) + li);
        }
#pragma unroll
        for (int j = 0; j < 8; j++) {
            __half2* hp = (__half2*)&v[j];
#pragma unroll
            for (int t = 0; t < 4; t++) {
                float2 f = __half22float2(hp[t]);
                acc[2 * t]     += f.x;
                acc[2 * t + 1] += f.y;
            }
        }
    }

#pragma unroll
    for (int k = 0; k < 8; k++) {
        acc[k] += __shfl_xor_sync(0xFFFFFFFFu, acc[k], 8);
        acc[k] += __shfl_xor_sync(0xFFFFFFFFu, acc[k], 16);
    }

    if (g == 0) {
        float dv = g_dinv[node];
        float4 ba = ((const float4*)b1)[li * 2];
        float4 bb = ((const float4*)b1)[li * 2 + 1];
        __half2 h[4];
        h[0] = __floats2half2_rn(fmaxf(dv * acc[0] + ba.x, 0.f), fmaxf(dv * acc[1] + ba.y, 0.f));
        h[1] = __floats2half2_rn(fmaxf(dv * acc[2] + ba.z, 0.f), fmaxf(dv * acc[3] + ba.w, 0.f));
        h[2] = __floats2half2_rn(fmaxf(dv * acc[4] + bb.x, 0.f), fmaxf(dv * acc[5] + bb.y, 0.f));
        h[3] = __floats2half2_rn(fmaxf(dv * acc[6] + bb.z, 0.f), fmaxf(dv * acc[7] + bb.w, 0.f));
        *((uint4*)(g_hr + (size_t)node * 64) + li) = *(uint4*)h;
    }
}

// ------- GEMM2 tensor cores: h2' = dinv * (h_r @ W2), fp16 out, 128B rows ------
__global__ __launch_bounds__(256) void k_gemm2_tc() {
    __shared__ __align__(16) char sraw[46080];
    __half* ws = (__half*)sraw;                 // [64][72]  9216B
    __half* hs = (__half*)(sraw + 9216);        // [256][72] 36864B
    float*  fb = (float*)sraw;                  // aliased

    int tid  = threadIdx.x;
    int warp = tid >> 5;
    int lane = tid & 31;
    int nodebase = blockIdx.x * 256;

    for (int u = tid; u < 384; u += 256) {
        int r = u / 6, c = u % 6;
        uint4 v = ((const uint4*)g_w2h)[u];
        *(uint4*)(ws + r * XS_LD + c * 8) = v;
    }
#pragma unroll
    for (int i = 0; i < 8; i++) {
        int u = tid + i * 256;
        int r = u >> 3, c = u & 7;
        int node = nodebase + r;
        uint4 v = make_uint4(0u, 0u, 0u, 0u);
        if (node < N_NODES)
            v = *((const uint4*)(g_hr + (size_t)node * 64) + c);
        *(uint4*)(hs + r * XS_LD + c * 8) = v;
    }
    __syncthreads();

    wmma::fragment<wmma::accumulator, 16, 16, 16, float> c[2][3];
#pragma unroll
    for (int p = 0; p < 2; p++)
#pragma unroll
        for (int ct = 0; ct < 3; ct++) wmma::fill_fragment(c[p][ct], 0.f);

#pragma unroll
    for (int kt = 0; kt < 4; kt++) {
        wmma::fragment<wmma::matrix_a, 16, 16, 16, __half, wmma::row_major> a0, a1;
        wmma::load_matrix_sync(a0, hs + (warp * 32 +  0) * XS_LD + kt * 16, XS_LD);
        wmma::load_matrix_sync(a1, hs + (warp * 32 + 16) * XS_LD + kt * 16, XS_LD);
#pragma unroll
        for (int ct = 0; ct < 3; ct++) {
            wmma::fragment<wmma::matrix_b, 16, 16, 16, __half, wmma::row_major> b;
            wmma::load_matrix_sync(b, ws + kt * 16 * XS_LD + ct * 16, XS_LD);
            wmma::mma_sync(c[0][ct], a0, b, c[0][ct]);
            wmma::mma_sync(c[1][ct], a1, b, c[1][ct]);
        }
    }
    __syncthreads();

    float* myfb = fb + warp * 16 * 64;
#pragma unroll
    for (int p = 0; p < 2; p++) {
#pragma unroll
        for (int ct = 0; ct < 3; ct++)
            wmma::store_matrix_sync(myfb + ct * 16, c[p][ct], 64, wmma::mem_row_major);
        __syncwarp();

        int row = lane >> 1;
        int ph  = lane & 1;
        int node = nodebase + warp * 32 + p * 16 + row;
        if (node < N_NODES) {
            float dv = g_dinv[node];               // pre-scale for layer-2 gather
            const float* fr = myfb + row * 64 + ph * 20;
            __half2* o = &g_h2[(size_t)node * 32 + ph * 10];   // 128B-padded rows
#pragma unroll
            for (int j = 0; j < 10; j++)
                o[j] = __floats2half2_rn(dv * fr[2 * j], dv * fr[2 * j + 1]);
        }
        __syncwarp();
    }
}

// -- layer-2 aggregation + dinv + b2 + log-softmax: warp/node, 4 edges/warp-load --
__global__ __launch_bounds__(256) void k_agg2(float* __restrict__ out,
                                              const float* __restrict__ b2) {
    int node = (blockIdx.x * 256 + threadIdx.x) >> 5;
    int lane = threadIdx.x & 31;
    if (node >= N_NODES) return;
    int g  = lane >> 3;
    int li = lane & 7;
    bool fvalid = (li < 5);

    float acc[8];
    {
        uint4 sv = make_uint4(0u, 0u, 0u, 0u);
        if (fvalid) sv = *((const uint4*)(g_h2 + (size_t)node * 32) + li);
        __half2* hp = (__half2*)&sv;
        float m0 = (g == 0) ? 1.f : 0.f;
#pragma unroll
        for (int t = 0; t < 4; t++) {
            float2 f = __half22float2(hp[t]);
            acc[2 * t]     = m0 * f.x;
            acc[2 * t + 1] = m0 * f.y;
        }
    }

    int start = g_rowptr[node];
    int cnt   = g_dege[node];
    for (int base = 0; base < cnt; base += 32) {
        int idx = base + lane;
        int rec = (idx < cnt) ? g_srcs[start + idx] : -1;
        uint4 v[8];
#pragma unroll
        for (int j = 0; j < 8; j++) {
            int src = __shfl_sync(0xFFFFFFFFu, rec, 4 * j + g);
            v[j] = make_uint4(0u, 0u, 0u, 0u);
            if (fvalid && src >= 0)
                v[j] = *((const uint4*)(g_h2 + (size_t)src * 32) + li);
        }
#pragma unroll
        for (int j = 0; j < 8; j++) {
            __half2* hp = (__half2*)&v[j];
#pragma unroll
            for (int t = 0; t < 4; t++) {
                float2 f = __half22float2(hp[t]);
                acc[2 * t]     += f.x;
                acc[2 * t + 1] += f.y;
            }
        }
    }

#pragma unroll
    for (int k = 0; k < 8; k++) {
        acc[k] += __shfl_xor_sync(0xFFFFFFFFu, acc[k], 8);
        acc[k] += __shfl_xor_sync(0xFFFFFFFFu, acc[k], 16);
    }

    bool own = (g == 0) && fvalid;
    float vals[8];
    if (own) {
        float dv = g_dinv[node];
        float4 ba = ((const float4*)b2)[li * 2];
        float4 bb = ((const float4*)b2)[li * 2 + 1];
        vals[0] = dv * acc[0] + ba.x; vals[1] = dv * acc[1] + ba.y;
        vals[2] = dv * acc[2] + ba.z; vals[3] = dv * acc[3] + ba.w;
        vals[4] = dv * acc[4] + bb.x; vals[5] = dv * acc[5] + bb.y;
        vals[6] = dv * acc[6] + bb.z; vals[7] = dv * acc[7] + bb.w;
    } else {
#pragma unroll
        for (int k = 0; k < 8; k++) vals[k] = -3.4e38f;
    }

    float mx = vals[0];
#pragma unroll
    for (int k = 1; k < 8; k++) mx = fmaxf(mx, vals[k]);
#pragma unroll
    for (int o = 16; o > 0; o >>= 1)
        mx = fmaxf(mx, __shfl_xor_sync(0xFFFFFFFFu, mx, o));

    float s = 0.f;
    if (own) {
#pragma unroll
        for (int k = 0; k < 8; k++) s += expf(vals[k] - mx);
    }
#pragma unroll
    for (int o = 16; o > 0; o >>= 1)
        s += __shfl_xor_sync(0xFFFFFFFFu, s, o);

    float ls = logf(s) + mx;
    if (own) {
        float4* o0 = (float4*)(out + (size_t)node * 40 + li * 8);
        o0[0] = make_float4(vals[0] - ls, vals[1] - ls, vals[2] - ls, vals[3] - ls);
        o0[1] = make_float4(vals[4] - ls, vals[5] - ls, vals[6] - ls, vals[7] - ls);
    }
}

// ---------------- launch ----------------
extern "C" void kernel_launch(void* const* d_in, const int* in_sizes, int n_in,
                              void* d_out, int out_size) {
    const float* x  = (const float*)d_in[0];
    const int*   ei = (const int*)d_in[1];   // int32 (JAX x64 disabled)
    const float* W1 = (const float*)d_in[2];
    const float* b1 = (const float*)d_in[3];
    const float* W2 = (const float*)d_in[4];
    const float* b2 = (const float*)d_in[5];
    float*       out = (float*)d_out;

    // Host-side attribute; executes immediately even under capture; idempotent.
    cudaFuncSetAttribute(k_gemm1_tc, cudaFuncAttributeMaxDynamicSharedMemorySize, SM_TOT);

    const int TB = 256;
    k_prep0       <<<(N_NODES + TB - 1) / TB, TB>>>(W1, W2);
    k_count_deg   <<<(N_EDGES + TB - 1) / TB, TB>>>(ei);
    k_convx_scaled<<<(int)(((size_t)N_NODES * F_IN / 8 + TB - 1) / TB), TB>>>(x);
    // 4th launch = ncu capture slot: gemm1_tc (cp.async double-buffered)
    k_gemm1_tc    <<<(N_NODES + 255) / 256, 256, SM_TOT>>>();
    k_scan1       <<<N_SCANB, SCAN_B>>>();
    k_scan2       <<<1, 256>>>();
    k_scan3       <<<(N_NODES + TB - 1) / TB, TB>>>();
    k_sort        <<<(N_EDGES + TB - 1) / TB, TB>>>(ei);

    k_agg1        <<<(N_NODES * 32 + TB - 1) / TB, TB>>>(b1);
    k_gemm2_tc    <<<(N_NODES + 255) / 256, 256>>>();
    k_agg2        <<<(N_NODES * 32 + TB - 1) / TB, TB>>>(out, b2);
}